// round 1
// baseline (speedup 1.0000x reference)
#include <cuda_runtime.h>
#include <math.h>

// Problem dims (fixed by the dataset):
//   queries      : [Q=512, D=1024]  fp32
//   local_tokens : [B=64, L=1024, D=1024] fp32
//   out          : [Q=512, B=64]    fp32, out[q*64 + b]
//
// Per CTA: one (b, 32-query tile).
//   Phase 1: S[32][1024] = Qtile @ tokens[b]^T / 32        (SMEM-resident)
//   Phase 2: row softmax of S in SMEM
//   Phase 3: agg = S @ tokens[b]  computed in register d-blocks; fold into
//            cosine epilogue (dot(q,agg), ||agg||, ||q||) -> out[q][b].

#define QT  32      // query rows per CTA
#define NB  256     // N-block (L cols in phase 1, D cols in phase 3)
#define KC  32      // K chunk
#define NT  256     // threads per CTA

static constexpr int Dd = 1024;
static constexpr int Ld = 1024;
static constexpr int Bn = 64;

// SMEM layout (floats):
//   S  : QT * 1024            = 32768
//   Qs : 32 * 33              = 1056
//   Ts : max(256*33, 32*256)  = 8448
static constexpr int S_ELEMS  = QT * 1024;
static constexpr int QS_ELEMS = 32 * 33;
static constexpr int TS_ELEMS = 256 * 33;
static constexpr int SMEM_FLOATS = S_ELEMS + QS_ELEMS + TS_ELEMS;
static constexpr int SMEM_BYTES  = SMEM_FLOATS * 4;   // 169,088 B

__global__ void __launch_bounds__(NT, 1)
simlogit_kernel(const float* __restrict__ queries,
                const float* __restrict__ tokens,
                float* __restrict__ out)
{
    extern __shared__ float smem[];
    float* S  = smem;                 // [32][1024]
    float* Qs = S + S_ELEMS;          // [32][33]
    float* Ts = Qs + QS_ELEMS;        // [256][33] or [32][256]

    const int b  = blockIdx.y;
    const int q0 = blockIdx.x * QT;
    const int tid = threadIdx.x;
    const int tx  = tid & 31;
    const int ty  = tid >> 5;         // warp id, 0..7

    const float* __restrict__ tokB = tokens + (size_t)b * Ld * Dd;

    // ---------------- Phase 1: S = Qtile @ tokB^T * (1/32) ----------------
    for (int n0 = 0; n0 < Ld; n0 += NB) {
        float acc[4][8];
        #pragma unroll
        for (int i = 0; i < 4; i++)
            #pragma unroll
            for (int j = 0; j < 8; j++) acc[i][j] = 0.0f;

        for (int k0 = 0; k0 < Dd; k0 += KC) {
            // Stage Qs[32][32] (rows = q, cols = k), padded stride 33
            #pragma unroll
            for (int i = 0; i < 4; i++) {
                int idx = i * NT + tid;
                int r = idx >> 5, c = idx & 31;
                Qs[r * 33 + c] = queries[(size_t)(q0 + r) * Dd + k0 + c];
            }
            // Stage Ts[256][32] (rows = l, cols = k), padded stride 33
            #pragma unroll
            for (int i = 0; i < 32; i++) {
                int idx = i * NT + tid;
                int r = idx >> 5, c = idx & 31;
                Ts[r * 33 + c] = tokB[(size_t)(n0 + r) * Dd + k0 + c];
            }
            __syncthreads();

            #pragma unroll
            for (int k = 0; k < KC; k++) {
                float qv[4], tv[8];
                #pragma unroll
                for (int i = 0; i < 4; i++) qv[i] = Qs[(ty * 4 + i) * 33 + k];
                #pragma unroll
                for (int j = 0; j < 8; j++) tv[j] = Ts[(tx + 32 * j) * 33 + k];
                #pragma unroll
                for (int i = 0; i < 4; i++)
                    #pragma unroll
                    for (int j = 0; j < 8; j++)
                        acc[i][j] = fmaf(qv[i], tv[j], acc[i][j]);
            }
            __syncthreads();
        }

        const float inv_sqrtD = 1.0f / 32.0f;   // 1/sqrt(1024)
        #pragma unroll
        for (int i = 0; i < 4; i++)
            #pragma unroll
            for (int j = 0; j < 8; j++)
                S[(ty * 4 + i) * 1024 + n0 + tx + 32 * j] = acc[i][j] * inv_sqrtD;
    }
    __syncthreads();

    // ---------------- Phase 2: row softmax (warp ty owns rows 4ty..4ty+3) --
    #pragma unroll
    for (int i = 0; i < 4; i++) {
        float* row = S + (ty * 4 + i) * 1024;
        float m = -INFINITY;
        #pragma unroll
        for (int j = 0; j < 32; j++) m = fmaxf(m, row[tx + 32 * j]);
        #pragma unroll
        for (int o = 16; o > 0; o >>= 1)
            m = fmaxf(m, __shfl_xor_sync(0xffffffffu, m, o));

        float s = 0.0f;
        #pragma unroll
        for (int j = 0; j < 32; j++) {
            float v = expf(row[tx + 32 * j] - m);
            row[tx + 32 * j] = v;
            s += v;
        }
        #pragma unroll
        for (int o = 16; o > 0; o >>= 1)
            s += __shfl_xor_sync(0xffffffffu, s, o);

        float invs = 1.0f / s;
        #pragma unroll
        for (int j = 0; j < 32; j++) row[tx + 32 * j] *= invs;
    }
    __syncthreads();

    // ---------------- Phase 3: agg = attn @ tokB, fused cosine epilogue ----
    float dotA[4] = {0, 0, 0, 0};
    float na2[4]  = {0, 0, 0, 0};
    float nq2[4]  = {0, 0, 0, 0};

    for (int n0 = 0; n0 < Dd; n0 += NB) {
        float acc[4][8];
        #pragma unroll
        for (int i = 0; i < 4; i++)
            #pragma unroll
            for (int j = 0; j < 8; j++) acc[i][j] = 0.0f;

        for (int k0 = 0; k0 < Ld; k0 += KC) {
            // Stage Ts[32][256] (rows = l (k), cols = d), stride 256
            #pragma unroll
            for (int i = 0; i < 32; i++)
                Ts[i * NB + tid] = tokB[(size_t)(k0 + i) * Dd + n0 + tid];
            __syncthreads();

            #pragma unroll
            for (int k = 0; k < KC; k++) {
                float av[4], bv[8];
                #pragma unroll
                for (int i = 0; i < 4; i++)
                    av[i] = S[(ty * 4 + i) * 1024 + k0 + k];   // broadcast
                #pragma unroll
                for (int j = 0; j < 8; j++)
                    bv[j] = Ts[k * NB + tx + 32 * j];
                #pragma unroll
                for (int i = 0; i < 4; i++)
                    #pragma unroll
                    for (int j = 0; j < 8; j++)
                        acc[i][j] = fmaf(av[i], bv[j], acc[i][j]);
            }
            __syncthreads();
        }

        // Fold this d-block of agg into cosine accumulators
        #pragma unroll
        for (int i = 0; i < 4; i++) {
            const int q = q0 + ty * 4 + i;
            #pragma unroll
            for (int j = 0; j < 8; j++) {
                const int d = n0 + tx + 32 * j;
                float qv = queries[(size_t)q * Dd + d];
                float a  = acc[i][j];
                dotA[i] = fmaf(qv, a, dotA[i]);
                na2[i]  = fmaf(a,  a, na2[i]);
                nq2[i]  = fmaf(qv, qv, nq2[i]);
            }
        }
    }

    // Warp-reduce the 3 scalars per row; lane 0 writes out[q][b]
    #pragma unroll
    for (int i = 0; i < 4; i++) {
        float d_ = dotA[i], a2 = na2[i], q2 = nq2[i];
        #pragma unroll
        for (int o = 16; o > 0; o >>= 1) {
            d_ += __shfl_xor_sync(0xffffffffu, d_, o);
            a2 += __shfl_xor_sync(0xffffffffu, a2, o);
            q2 += __shfl_xor_sync(0xffffffffu, q2, o);
        }
        if (tx == 0) {
            float nq = fmaxf(sqrtf(q2), 1e-12f);
            float na = fmaxf(sqrtf(a2), 1e-12f);
            out[(size_t)(q0 + ty * 4 + i) * Bn + b] = d_ / (nq * na);
        }
    }
}

extern "C" void kernel_launch(void* const* d_in, const int* in_sizes, int n_in,
                              void* d_out, int out_size)
{
    const float* queries = (const float*)d_in[0];   // [512, 1024]
    const float* tokens  = (const float*)d_in[1];   // [64, 1024, 1024]
    float* out = (float*)d_out;                     // [512, 64]

    cudaFuncSetAttribute(simlogit_kernel,
                         cudaFuncAttributeMaxDynamicSharedMemorySize,
                         SMEM_BYTES);

    dim3 grid(512 / QT, Bn);   // x = q-tiles (16), y = batch (64) -> same-b CTAs adjacent for L2 reuse
    simlogit_kernel<<<grid, NT, SMEM_BYTES>>>(queries, tokens, out);
}

// round 4
// speedup vs baseline: 3.7850x; 3.7850x over previous
#include <cuda_runtime.h>
#include <cuda_bf16.h>
#include <cstdint>
#include <math.h>

// SimilarityLogit on GB300 via mma.sync (HMMA) bf16 split-precision GEMMs.
//   queries      : [Q=512, D=1024]  fp32      (d_in[0])
//   local_tokens : [B=64, L=1024, D=1024] fp32 (d_in[1])
//   out          : [Q=512, B=64]   fp32  (out[q*64+b])
//
// K0a: queries -> Qh,Ql bf16 (K-major)
// K0b: tokens  -> TKh,TKl ([b][l][d]) and TNh,TNl ([b][d][l])
// K1 : S = (Qh Th + Qh Tl + Ql Th)/32          (mma.sync, fp32 accum)
// K2 : softmax rows of S -> Ph,Pl bf16
// K3 : AGG = P @ T (via TN)                    (mma.sync, fp32 accum)
// K4 : cosine(q, agg) -> out[q][b]

static constexpr int Qn = 512, Dn = 1024, Ln = 1024, Bn = 64;

// ---------------- scratch (device globals; no runtime allocation) ----------
__device__ __nv_bfloat16 g_Qh[(size_t)Qn * Dn];
__device__ __nv_bfloat16 g_Ql[(size_t)Qn * Dn];
__device__ __nv_bfloat16 g_TKh[(size_t)Bn * Ln * Dn];
__device__ __nv_bfloat16 g_TKl[(size_t)Bn * Ln * Dn];
__device__ __nv_bfloat16 g_TNh[(size_t)Bn * Dn * Ln];
__device__ __nv_bfloat16 g_TNl[(size_t)Bn * Dn * Ln];
__device__ float         g_S[(size_t)Bn * Qn * Ln];
__device__ __nv_bfloat16 g_Ph[(size_t)Bn * Qn * Ln];
__device__ __nv_bfloat16 g_Pl[(size_t)Bn * Qn * Ln];
__device__ float         g_AGG[(size_t)Bn * Qn * Dn];

// ---------------- PTX helpers ----------------------------------------------
__device__ __forceinline__ uint32_t smem_u32(const void* p) {
    uint32_t a;
    asm("{ .reg .u64 t; cvta.to.shared.u64 t, %1; cvt.u32.u64 %0, t; }"
        : "=r"(a) : "l"(p));
    return a;
}

__device__ __forceinline__ void cp_async16(uint32_t dst, const void* src) {
    asm volatile("cp.async.cg.shared.global [%0], [%1], 16;"
                 :: "r"(dst), "l"(src) : "memory");
}
__device__ __forceinline__ void cp_commit() {
    asm volatile("cp.async.commit_group;" ::: "memory");
}
template <int N>
__device__ __forceinline__ void cp_wait() {
    asm volatile("cp.async.wait_group %0;" :: "n"(N) : "memory");
}

__device__ __forceinline__ void ldsm_x4(uint32_t* r, uint32_t addr) {
    asm volatile("ldmatrix.sync.aligned.m8n8.x4.shared.b16 {%0,%1,%2,%3}, [%4];"
                 : "=r"(r[0]), "=r"(r[1]), "=r"(r[2]), "=r"(r[3]) : "r"(addr));
}

__device__ __forceinline__ void mma16816(float* c, const uint32_t* a, const uint32_t* b) {
    asm volatile(
        "mma.sync.aligned.m16n8k16.row.col.f32.bf16.bf16.f32 "
        "{%0,%1,%2,%3}, {%4,%5,%6,%7}, {%8,%9}, {%0,%1,%2,%3};"
        : "+f"(c[0]), "+f"(c[1]), "+f"(c[2]), "+f"(c[3])
        : "r"(a[0]), "r"(a[1]), "r"(a[2]), "r"(a[3]), "r"(b[0]), "r"(b[1]));
}

__device__ __forceinline__ uint32_t sw128(uint32_t off) {
    return off ^ ((off >> 3) & 0x70);
}

// ---------------- split helpers --------------------------------------------
__device__ __forceinline__ void split1(float x, __nv_bfloat16& h, __nv_bfloat16& l) {
    h = __float2bfloat16(x);
    l = __float2bfloat16(x - __bfloat162float(h));
}

// ---------------- K0a: convert queries -------------------------------------
__global__ void convert_q_kernel(const float* __restrict__ q) {
    int idx = blockIdx.x * blockDim.x + threadIdx.x;   // float4 index, 131072 total
    float4 v = ((const float4*)q)[idx];
    __nv_bfloat16 h[4], l[4];
    split1(v.x, h[0], l[0]); split1(v.y, h[1], l[1]);
    split1(v.z, h[2], l[2]); split1(v.w, h[3], l[3]);
    uint2 hp, lp;
    hp.x = (uint32_t)__bfloat16_as_ushort(h[0]) | ((uint32_t)__bfloat16_as_ushort(h[1]) << 16);
    hp.y = (uint32_t)__bfloat16_as_ushort(h[2]) | ((uint32_t)__bfloat16_as_ushort(h[3]) << 16);
    lp.x = (uint32_t)__bfloat16_as_ushort(l[0]) | ((uint32_t)__bfloat16_as_ushort(l[1]) << 16);
    lp.y = (uint32_t)__bfloat16_as_ushort(l[2]) | ((uint32_t)__bfloat16_as_ushort(l[3]) << 16);
    ((uint2*)g_Qh)[idx] = hp;
    ((uint2*)g_Ql)[idx] = lp;
}

// ---------------- K0b: convert + transpose tokens --------------------------
__global__ void convert_tok_kernel(const float* __restrict__ tok) {
    __shared__ float tile[32][33];
    const int b = blockIdx.z;
    const int d0 = blockIdx.x * 32, l0 = blockIdx.y * 32;
    const int tx = threadIdx.x & 31, ty = threadIdx.x >> 5;  // ty 0..7

    const float* src = tok + ((size_t)b * Ln + l0) * Dn + d0;
    #pragma unroll
    for (int r = 0; r < 4; r++) {
        int ll = ty + r * 8;
        float x = src[(size_t)ll * Dn + tx];
        tile[ll][tx] = x;
        __nv_bfloat16 h, l; split1(x, h, l);
        size_t o = ((size_t)b * Ln + l0 + ll) * Dn + d0 + tx;
        g_TKh[o] = h; g_TKl[o] = l;
    }
    __syncthreads();
    #pragma unroll
    for (int r = 0; r < 4; r++) {
        int dd = ty + r * 8;
        float x = tile[tx][dd];          // tokens[l0+tx][d0+dd]
        __nv_bfloat16 h, l; split1(x, h, l);
        size_t o = ((size_t)b * Dn + d0 + dd) * Ln + l0 + tx;
        g_TNh[o] = h; g_TNl[o] = l;
    }
}

// ---------------- K2: softmax + split --------------------------------------
__global__ void softmax_kernel() {
    const int tid = threadIdx.x;
    float* row = g_S + (size_t)blockIdx.x * Ln;
    float4 v = ((float4*)row)[tid];

    __shared__ float sred[8];
    __shared__ float bc;

    float m = fmaxf(fmaxf(v.x, v.y), fmaxf(v.z, v.w));
    #pragma unroll
    for (int o = 16; o > 0; o >>= 1) m = fmaxf(m, __shfl_xor_sync(0xffffffffu, m, o));
    if ((tid & 31) == 0) sred[tid >> 5] = m;
    __syncthreads();
    if (tid == 0) {
        float t = sred[0];
        #pragma unroll
        for (int i = 1; i < 8; i++) t = fmaxf(t, sred[i]);
        bc = t;
    }
    __syncthreads();
    m = bc;
    __syncthreads();   // protect sred reuse

    float4 e;
    e.x = expf(v.x - m); e.y = expf(v.y - m);
    e.z = expf(v.z - m); e.w = expf(v.w - m);
    float s = e.x + e.y + e.z + e.w;
    #pragma unroll
    for (int o = 16; o > 0; o >>= 1) s += __shfl_xor_sync(0xffffffffu, s, o);
    if ((tid & 31) == 0) sred[tid >> 5] = s;
    __syncthreads();
    if (tid == 0) {
        float t = 0.f;
        #pragma unroll
        for (int i = 0; i < 8; i++) t += sred[i];
        bc = t;
    }
    __syncthreads();
    float inv = 1.0f / bc;

    __nv_bfloat16 h[4], l[4];
    split1(e.x * inv, h[0], l[0]); split1(e.y * inv, h[1], l[1]);
    split1(e.z * inv, h[2], l[2]); split1(e.w * inv, h[3], l[3]);
    uint2 hp, lp;
    hp.x = (uint32_t)__bfloat16_as_ushort(h[0]) | ((uint32_t)__bfloat16_as_ushort(h[1]) << 16);
    hp.y = (uint32_t)__bfloat16_as_ushort(h[2]) | ((uint32_t)__bfloat16_as_ushort(h[3]) << 16);
    lp.x = (uint32_t)__bfloat16_as_ushort(l[0]) | ((uint32_t)__bfloat16_as_ushort(l[1]) << 16);
    lp.y = (uint32_t)__bfloat16_as_ushort(l[2]) | ((uint32_t)__bfloat16_as_ushort(l[3]) << 16);
    size_t base = (size_t)blockIdx.x * Ln + tid * 4;
    *(uint2*)(g_Ph + base) = hp;
    *(uint2*)(g_Pl + base) = lp;
}

// ---------------- GEMM core (K1: MODE=0, K3: MODE=1) ------------------------
// CTA tile 128x128, K chunks of 64. SMEM double-buffered:
//   buf: Ah(16K) Al(16K) Bh(16K) Bl(16K) = 64K; x2 = 128K.
// 8 warps in 2x4, warp tile 64x32.
static constexpr uint32_t OFF_AL = 16384;
static constexpr uint32_t OFF_BH = 32768;
static constexpr uint32_t OFF_BL = 49152;
static constexpr uint32_t BUFSZ  = 65536;
static constexpr int GEMM_SMEM = 131072;

__device__ __forceinline__ void stage_chunk(
    uint32_t sbuf,
    const __nv_bfloat16* Ah, const __nv_bfloat16* Al,
    const __nv_bfloat16* Bh, const __nv_bfloat16* Bl,
    int k0, int tid)
{
    #pragma unroll
    for (int i = 0; i < 4; i++) {
        int g = tid + i * 256;          // 0..1023
        int row = g >> 3, kg = g & 7;   // 128 rows x 8 granules(16B)
        uint32_t sw = sw128((uint32_t)row * 128 + kg * 16);
        size_t src = (size_t)row * 1024 + k0 + kg * 8;
        cp_async16(sbuf + sw,           Ah + src);
        cp_async16(sbuf + OFF_AL + sw,  Al + src);
        cp_async16(sbuf + OFF_BH + sw,  Bh + src);
        cp_async16(sbuf + OFF_BL + sw,  Bl + src);
    }
}

template <int MODE>
__global__ void __launch_bounds__(256, 1)
gemm_kernel(float* __restrict__ unused)
{
    extern __shared__ unsigned char smem[];
    const uint32_t sbase = smem_u32(smem);
    const int tid  = threadIdx.x;
    const int wid  = tid >> 5, lane = tid & 31;
    const int q0   = blockIdx.x * 128;
    const int n0   = blockIdx.y * 128;
    const int b    = blockIdx.z;

    const __nv_bfloat16 *Ah, *Al, *Bh, *Bl;
    float* Cg;
    float scale;
    if (MODE == 0) {
        Ah = g_Qh + (size_t)q0 * Dn;
        Al = g_Ql + (size_t)q0 * Dn;
        Bh = g_TKh + (size_t)b * Ln * Dn + (size_t)n0 * Dn;
        Bl = g_TKl + (size_t)b * Ln * Dn + (size_t)n0 * Dn;
        Cg = g_S + ((size_t)b * Qn + q0) * Ln + n0;
        scale = 0.03125f;               // 1/sqrt(1024)
    } else {
        Ah = g_Ph + ((size_t)b * Qn + q0) * Ln;
        Al = g_Pl + ((size_t)b * Qn + q0) * Ln;
        Bh = g_TNh + (size_t)b * Dn * Ln + (size_t)n0 * Ln;
        Bl = g_TNl + (size_t)b * Dn * Ln + (size_t)n0 * Ln;
        Cg = g_AGG + ((size_t)b * Qn + q0) * Dn + n0;
        scale = 1.0f;
    }

    const int wm = wid >> 2;            // 0..1  (64-row slab)
    const int wn = wid & 3;             // 0..3  (32-col slab)

    // ldmatrix lane address components (non-trans, K-major storage)
    const int arow  = wm * 64 + (lane & 7) + ((lane >> 3) & 1) * 8;
    const int acol8 = (lane >> 4) * 8;
    const int brow  = wn * 32 + (lane & 7) + (lane >> 4) * 8;
    const int bcol8 = ((lane >> 3) & 1) * 8;

    float c[4][4][4];
    #pragma unroll
    for (int mt = 0; mt < 4; mt++)
        #pragma unroll
        for (int nt = 0; nt < 4; nt++)
            #pragma unroll
            for (int i = 0; i < 4; i++) c[mt][nt][i] = 0.f;

    stage_chunk(sbase, Ah, Al, Bh, Bl, 0, tid);
    cp_commit();

    int buf = 0;
    for (int kc = 0; kc < 16; kc++) {
        if (kc + 1 < 16) {
            stage_chunk(sbase + (buf ^ 1) * BUFSZ, Ah, Al, Bh, Bl, (kc + 1) * 64, tid);
            cp_commit();
            cp_wait<1>();
        } else {
            cp_wait<0>();
        }
        __syncthreads();

        const uint32_t base = sbase + buf * BUFSZ;
        #pragma unroll
        for (int ks = 0; ks < 4; ks++) {
            const int kb = ks * 16;
            uint32_t ah[4][4], al[4][4], bh[4][2], bl[4][2];
            #pragma unroll
            for (int mt = 0; mt < 4; mt++) {
                uint32_t sw = sw128((uint32_t)(arow + mt * 16) * 128 + (acol8 + kb) * 2);
                ldsm_x4(ah[mt], base + sw);
                ldsm_x4(al[mt], base + OFF_AL + sw);
            }
            #pragma unroll
            for (int bt = 0; bt < 2; bt++) {
                uint32_t sw = sw128((uint32_t)(brow + bt * 16) * 128 + (bcol8 + kb) * 2);
                uint32_t t[4];
                ldsm_x4(t, base + OFF_BH + sw);
                bh[bt * 2][0] = t[0]; bh[bt * 2][1] = t[1];
                bh[bt * 2 + 1][0] = t[2]; bh[bt * 2 + 1][1] = t[3];
                ldsm_x4(t, base + OFF_BL + sw);
                bl[bt * 2][0] = t[0]; bl[bt * 2][1] = t[1];
                bl[bt * 2 + 1][0] = t[2]; bl[bt * 2 + 1][1] = t[3];
            }
            #pragma unroll
            for (int mt = 0; mt < 4; mt++)
                #pragma unroll
                for (int nt = 0; nt < 4; nt++) {
                    mma16816(c[mt][nt], ah[mt], bh[nt]);
                    mma16816(c[mt][nt], ah[mt], bl[nt]);
                    mma16816(c[mt][nt], al[mt], bh[nt]);
                }
        }
        __syncthreads();
        buf ^= 1;
    }

    // Epilogue: write fp32 C tile
    const int r0 = lane >> 2, c0 = (lane & 3) * 2;
    #pragma unroll
    for (int mt = 0; mt < 4; mt++) {
        #pragma unroll
        for (int nt = 0; nt < 4; nt++) {
            int row = wm * 64 + mt * 16 + r0;
            int col = wn * 32 + nt * 8 + c0;
            float2 v0 = make_float2(c[mt][nt][0] * scale, c[mt][nt][1] * scale);
            float2 v1 = make_float2(c[mt][nt][2] * scale, c[mt][nt][3] * scale);
            *(float2*)(Cg + (size_t)row * 1024 + col) = v0;
            *(float2*)(Cg + (size_t)(row + 8) * 1024 + col) = v1;
        }
    }
}

// ---------------- K4: cosine epilogue ---------------------------------------
__global__ void cosine_kernel(const float* __restrict__ queries,
                              float* __restrict__ out)
{
    const int warp = threadIdx.x >> 5, lane = threadIdx.x & 31;
    const int r = blockIdx.x * 8 + warp;      // 0..32767  (= b*512 + q)
    const int b = r >> 9;
    const int q = r & 511;

    const float4* agg = (const float4*)(g_AGG + (size_t)r * Dn);
    const float4* qp  = (const float4*)(queries + (size_t)q * Dn);

    float d = 0.f, a2 = 0.f, q2 = 0.f;
    #pragma unroll
    for (int i = 0; i < 8; i++) {
        int idx = lane + i * 32;
        float4 a = agg[idx];
        float4 qv = qp[idx];
        d  = fmaf(qv.x, a.x, fmaf(qv.y, a.y, fmaf(qv.z, a.z, fmaf(qv.w, a.w, d))));
        a2 = fmaf(a.x, a.x, fmaf(a.y, a.y, fmaf(a.z, a.z, fmaf(a.w, a.w, a2))));
        q2 = fmaf(qv.x, qv.x, fmaf(qv.y, qv.y, fmaf(qv.z, qv.z, fmaf(qv.w, qv.w, q2))));
    }
    #pragma unroll
    for (int o = 16; o > 0; o >>= 1) {
        d  += __shfl_xor_sync(0xffffffffu, d, o);
        a2 += __shfl_xor_sync(0xffffffffu, a2, o);
        q2 += __shfl_xor_sync(0xffffffffu, q2, o);
    }
    if (lane == 0) {
        float dn = fmaxf(sqrtf(q2), 1e-12f) * fmaxf(sqrtf(a2), 1e-12f);
        out[(size_t)q * Bn + b] = d / dn;
    }
}

// ---------------- launch ----------------------------------------------------
extern "C" void kernel_launch(void* const* d_in, const int* in_sizes, int n_in,
                              void* d_out, int out_size)
{
    const float* queries = (const float*)d_in[0];   // [512,1024]
    const float* tokens  = (const float*)d_in[1];   // [64,1024,1024]
    float* out = (float*)d_out;                     // [512,64]

    cudaFuncSetAttribute(gemm_kernel<0>,
                         cudaFuncAttributeMaxDynamicSharedMemorySize, GEMM_SMEM);
    cudaFuncSetAttribute(gemm_kernel<1>,
                         cudaFuncAttributeMaxDynamicSharedMemorySize, GEMM_SMEM);

    // K0a: queries -> Qh/Ql
    convert_q_kernel<<<131072 / 256, 256>>>(queries);
    // K0b: tokens -> TK + TN splits
    convert_tok_kernel<<<dim3(Dn / 32, Ln / 32, Bn), 256>>>(tokens);
    // K1: scores S
    gemm_kernel<0><<<dim3(Qn / 128, Ln / 128, Bn), 256, GEMM_SMEM>>>(nullptr);
    // K2: softmax + split P
    softmax_kernel<<<Bn * Qn, 256>>>();
    // K3: aggregate AGG
    gemm_kernel<1><<<dim3(Qn / 128, Dn / 128, Bn), 256, GEMM_SMEM>>>(nullptr);
    // K4: cosine -> out
    cosine_kernel<<<(Bn * Qn) / 8, 256>>>(queries, out);
}

// round 5
// speedup vs baseline: 4.9909x; 1.3186x over previous
#include <cuda_runtime.h>
#include <cuda_bf16.h>
#include <cstdint>
#include <math.h>

// SimilarityLogit on GB300 via mma.sync (HMMA) bf16 GEMMs.
//   queries      : [Q=512, D=1024]  fp32      (d_in[0])
//   local_tokens : [B=64, L=1024, D=1024] fp32 (d_in[1])
//   out          : [Q=512, B=64]   fp32  (out[q*64+b])
//
// Math: S = qT^t/32 ; P = softmax(S) ; agg = P T
//   out = dot(q,agg)/(max(||q||,eps) max(||agg||,eps))
// Identity: dot(q,agg) = 32 * sum_l P[l] S[l]  -> computed in softmax kernel.
// So GEMM2 only supplies ||agg||^2, which tolerates single-bf16 precision.
//
// K0a: queries -> Qh,Ql bf16 (3-term split for GEMM1 accuracy)
// K0b: ||q|| per row
// K0c: tokens -> TKh,TKl  ([b][l][d], B of GEMM1)
// K0d: tokens -> TNh      ([b][d][l], B of GEMM2, single bf16)
// K1 : S = (Qh Th + Qh Tl + Ql Th)/32       (3 MMA terms, fp32 accum)
// K2 : softmax rows of S -> Ph bf16 ; dot[b,q] = 32*sum P*S
// K3 : a2 partials = row sums of (Ph @ TNh)^2  (1 MMA term, no AGG write)
// K4 : out = dot / (||q|| * sqrt(a2))

static constexpr int Qn = 512, Dn = 1024, Ln = 1024, Bn = 64;

// ---------------- scratch (device globals; no runtime allocation) ----------
__device__ __nv_bfloat16 g_Qh[(size_t)Qn * Dn];
__device__ __nv_bfloat16 g_Ql[(size_t)Qn * Dn];
__device__ __nv_bfloat16 g_TKh[(size_t)Bn * Ln * Dn];
__device__ __nv_bfloat16 g_TKl[(size_t)Bn * Ln * Dn];
__device__ __nv_bfloat16 g_TNh[(size_t)Bn * Dn * Ln];
__device__ float         g_S[(size_t)Bn * Qn * Ln];
__device__ __nv_bfloat16 g_Ph[(size_t)Bn * Qn * Ln];
__device__ float         g_DOT[(size_t)Bn * Qn];
__device__ float         g_A2P[(size_t)Bn * 8 * Qn];   // per-(b, n-tile) row partials
__device__ float         g_QN[Qn];

// ---------------- PTX helpers ----------------------------------------------
__device__ __forceinline__ uint32_t smem_u32(const void* p) {
    uint32_t a;
    asm("{ .reg .u64 t; cvta.to.shared.u64 t, %1; cvt.u32.u64 %0, t; }"
        : "=r"(a) : "l"(p));
    return a;
}

__device__ __forceinline__ void cp_async16(uint32_t dst, const void* src) {
    asm volatile("cp.async.cg.shared.global [%0], [%1], 16;"
                 :: "r"(dst), "l"(src) : "memory");
}
__device__ __forceinline__ void cp_commit() {
    asm volatile("cp.async.commit_group;" ::: "memory");
}
template <int N>
__device__ __forceinline__ void cp_wait() {
    asm volatile("cp.async.wait_group %0;" :: "n"(N) : "memory");
}

__device__ __forceinline__ void ldsm_x4(uint32_t* r, uint32_t addr) {
    asm volatile("ldmatrix.sync.aligned.m8n8.x4.shared.b16 {%0,%1,%2,%3}, [%4];"
                 : "=r"(r[0]), "=r"(r[1]), "=r"(r[2]), "=r"(r[3]) : "r"(addr));
}

__device__ __forceinline__ void mma16816(float* c, const uint32_t* a, const uint32_t* b) {
    asm volatile(
        "mma.sync.aligned.m16n8k16.row.col.f32.bf16.bf16.f32 "
        "{%0,%1,%2,%3}, {%4,%5,%6,%7}, {%8,%9}, {%0,%1,%2,%3};"
        : "+f"(c[0]), "+f"(c[1]), "+f"(c[2]), "+f"(c[3])
        : "r"(a[0]), "r"(a[1]), "r"(a[2]), "r"(a[3]), "r"(b[0]), "r"(b[1]));
}

__device__ __forceinline__ uint32_t sw128(uint32_t off) {
    return off ^ ((off >> 3) & 0x70);
}

__device__ __forceinline__ void split1(float x, __nv_bfloat16& h, __nv_bfloat16& l) {
    h = __float2bfloat16(x);
    l = __float2bfloat16(x - __bfloat162float(h));
}

// ---------------- K0a: convert queries (hi/lo) ------------------------------
__global__ void convert_q_kernel(const float* __restrict__ q) {
    int idx = blockIdx.x * blockDim.x + threadIdx.x;   // float4 index
    float4 v = ((const float4*)q)[idx];
    __nv_bfloat16 h[4], l[4];
    split1(v.x, h[0], l[0]); split1(v.y, h[1], l[1]);
    split1(v.z, h[2], l[2]); split1(v.w, h[3], l[3]);
    uint2 hp, lp;
    hp.x = (uint32_t)__bfloat16_as_ushort(h[0]) | ((uint32_t)__bfloat16_as_ushort(h[1]) << 16);
    hp.y = (uint32_t)__bfloat16_as_ushort(h[2]) | ((uint32_t)__bfloat16_as_ushort(h[3]) << 16);
    lp.x = (uint32_t)__bfloat16_as_ushort(l[0]) | ((uint32_t)__bfloat16_as_ushort(l[1]) << 16);
    lp.y = (uint32_t)__bfloat16_as_ushort(l[2]) | ((uint32_t)__bfloat16_as_ushort(l[3]) << 16);
    ((uint2*)g_Qh)[idx] = hp;
    ((uint2*)g_Ql)[idx] = lp;
}

// ---------------- K0b: query norms ------------------------------------------
__global__ void qnorm_kernel(const float* __restrict__ q) {
    const int warp = threadIdx.x >> 5, lane = threadIdx.x & 31;
    const int row = blockIdx.x * 8 + warp;
    const float4* qp = (const float4*)(q + (size_t)row * Dn);
    float s = 0.f;
    #pragma unroll
    for (int i = 0; i < 8; i++) {
        float4 v = qp[lane + i * 32];
        s = fmaf(v.x, v.x, fmaf(v.y, v.y, fmaf(v.z, v.z, fmaf(v.w, v.w, s))));
    }
    #pragma unroll
    for (int o = 16; o > 0; o >>= 1) s += __shfl_xor_sync(0xffffffffu, s, o);
    if (lane == 0) g_QN[row] = sqrtf(s);
}

// ---------------- K0c: convert tokens (hi/lo, same layout) ------------------
__global__ void convert_tk_kernel(const float* __restrict__ tok) {
    size_t idx = (size_t)blockIdx.x * blockDim.x + threadIdx.x;   // float4 index
    float4 v = ((const float4*)tok)[idx];
    __nv_bfloat16 h[4], l[4];
    split1(v.x, h[0], l[0]); split1(v.y, h[1], l[1]);
    split1(v.z, h[2], l[2]); split1(v.w, h[3], l[3]);
    uint2 hp, lp;
    hp.x = (uint32_t)__bfloat16_as_ushort(h[0]) | ((uint32_t)__bfloat16_as_ushort(h[1]) << 16);
    hp.y = (uint32_t)__bfloat16_as_ushort(h[2]) | ((uint32_t)__bfloat16_as_ushort(h[3]) << 16);
    lp.x = (uint32_t)__bfloat16_as_ushort(l[0]) | ((uint32_t)__bfloat16_as_ushort(l[1]) << 16);
    lp.y = (uint32_t)__bfloat16_as_ushort(l[2]) | ((uint32_t)__bfloat16_as_ushort(l[3]) << 16);
    ((uint2*)g_TKh)[idx] = hp;
    ((uint2*)g_TKl)[idx] = lp;
}

// ---------------- K0d: transpose tokens -> TNh [b][d][l] (bf16) -------------
// Tile 64 l x 32 d. 256 threads.
__global__ void transpose_tn_kernel(const float* __restrict__ tok) {
    __shared__ float tile[64][33];
    const int b = blockIdx.z;
    const int d0 = blockIdx.x * 32, l0 = blockIdx.y * 64;
    const int t = threadIdx.x;

    const float* src = tok + ((size_t)b * Ln + l0) * Dn + d0;
    #pragma unroll
    for (int i = 0; i < 8; i++) {
        int e = t + i * 256;
        int l = e >> 5, d = e & 31;
        tile[l][d] = src[(size_t)l * Dn + d];
    }
    __syncthreads();
    #pragma unroll
    for (int p = 0; p < 4; p++) {
        int d = (t >> 5) + p * 8;
        int lp = (t & 31) * 2;
        __nv_bfloat162 v = __floats2bfloat162_rn(tile[lp][d], tile[lp + 1][d]);
        *(__nv_bfloat162*)(g_TNh + ((size_t)b * Dn + d0 + d) * Ln + l0 + lp) = v;
    }
}

// ---------------- K2: softmax + dot + split P -------------------------------
__global__ void softmax_kernel() {
    const int tid = threadIdx.x;
    const int row = blockIdx.x;                  // = b*Qn + q
    float* srow = g_S + (size_t)row * Ln;
    float4 v = ((float4*)srow)[tid];

    __shared__ float sred[8], sred2[8];
    __shared__ float bc, bc2;

    float m = fmaxf(fmaxf(v.x, v.y), fmaxf(v.z, v.w));
    #pragma unroll
    for (int o = 16; o > 0; o >>= 1) m = fmaxf(m, __shfl_xor_sync(0xffffffffu, m, o));
    if ((tid & 31) == 0) sred[tid >> 5] = m;
    __syncthreads();
    if (tid == 0) {
        float t = sred[0];
        #pragma unroll
        for (int i = 1; i < 8; i++) t = fmaxf(t, sred[i]);
        bc = t;
    }
    __syncthreads();
    m = bc;
    __syncthreads();   // protect sred reuse

    float4 e;
    e.x = expf(v.x - m); e.y = expf(v.y - m);
    e.z = expf(v.z - m); e.w = expf(v.w - m);
    float s  = e.x + e.y + e.z + e.w;
    float ev = e.x * v.x + e.y * v.y + e.z * v.z + e.w * v.w;
    #pragma unroll
    for (int o = 16; o > 0; o >>= 1) {
        s  += __shfl_xor_sync(0xffffffffu, s, o);
        ev += __shfl_xor_sync(0xffffffffu, ev, o);
    }
    if ((tid & 31) == 0) { sred[tid >> 5] = s; sred2[tid >> 5] = ev; }
    __syncthreads();
    if (tid == 0) {
        float t = 0.f, t2 = 0.f;
        #pragma unroll
        for (int i = 0; i < 8; i++) { t += sred[i]; t2 += sred2[i]; }
        bc = t; bc2 = t2;
    }
    __syncthreads();
    float inv = 1.0f / bc;
    if (tid == 0) g_DOT[row] = 32.0f * inv * bc2;   // dot(q, agg), exact identity

    __nv_bfloat16 h0 = __float2bfloat16(e.x * inv);
    __nv_bfloat16 h1 = __float2bfloat16(e.y * inv);
    __nv_bfloat16 h2 = __float2bfloat16(e.z * inv);
    __nv_bfloat16 h3 = __float2bfloat16(e.w * inv);
    uint2 hp;
    hp.x = (uint32_t)__bfloat16_as_ushort(h0) | ((uint32_t)__bfloat16_as_ushort(h1) << 16);
    hp.y = (uint32_t)__bfloat16_as_ushort(h2) | ((uint32_t)__bfloat16_as_ushort(h3) << 16);
    *(uint2*)(g_Ph + (size_t)row * Ln + tid * 4) = hp;
}

// ---------------- K1: GEMM1 (3-term split) ----------------------------------
// CTA tile 128x128, K chunks of 64. buf: Ah Al Bh Bl (16K each) x2 = 128K.
static constexpr uint32_t OFF_AL = 16384;
static constexpr uint32_t OFF_BH = 32768;
static constexpr uint32_t OFF_BL = 49152;
static constexpr uint32_t BUFSZ  = 65536;
static constexpr int GEMM1_SMEM = 131072;

__global__ void __launch_bounds__(256, 1)
gemm1_kernel()
{
    extern __shared__ unsigned char smem[];
    const uint32_t sbase = smem_u32(smem);
    const int tid  = threadIdx.x;
    const int wid  = tid >> 5, lane = tid & 31;
    const int q0   = blockIdx.x * 128;
    const int n0   = blockIdx.y * 128;
    const int b    = blockIdx.z;

    const __nv_bfloat16* Ah = g_Qh + (size_t)q0 * Dn;
    const __nv_bfloat16* Al = g_Ql + (size_t)q0 * Dn;
    const __nv_bfloat16* Bh = g_TKh + (size_t)b * Ln * Dn + (size_t)n0 * Dn;
    const __nv_bfloat16* Bl = g_TKl + (size_t)b * Ln * Dn + (size_t)n0 * Dn;
    float* Cg = g_S + ((size_t)b * Qn + q0) * Ln + n0;

    const int wm = wid >> 2, wn = wid & 3;
    const int arow  = wm * 64 + (lane & 7) + ((lane >> 3) & 1) * 8;
    const int acol8 = (lane >> 4) * 8;
    const int brow  = wn * 32 + (lane & 7) + (lane >> 4) * 8;
    const int bcol8 = ((lane >> 3) & 1) * 8;

    float c[4][4][4];
    #pragma unroll
    for (int mt = 0; mt < 4; mt++)
        #pragma unroll
        for (int nt = 0; nt < 4; nt++)
            #pragma unroll
            for (int i = 0; i < 4; i++) c[mt][nt][i] = 0.f;

    // stage chunk 0
    #pragma unroll
    for (int i = 0; i < 4; i++) {
        int g = tid + i * 256;
        int row = g >> 3, kg = g & 7;
        uint32_t sw = sw128((uint32_t)row * 128 + kg * 16);
        size_t src = (size_t)row * 1024 + kg * 8;
        cp_async16(sbase + sw,          Ah + src);
        cp_async16(sbase + OFF_AL + sw, Al + src);
        cp_async16(sbase + OFF_BH + sw, Bh + src);
        cp_async16(sbase + OFF_BL + sw, Bl + src);
    }
    cp_commit();

    int buf = 0;
    for (int kc = 0; kc < 16; kc++) {
        if (kc + 1 < 16) {
            uint32_t sb = sbase + (buf ^ 1) * BUFSZ;
            int k0 = (kc + 1) * 64;
            #pragma unroll
            for (int i = 0; i < 4; i++) {
                int g = tid + i * 256;
                int row = g >> 3, kg = g & 7;
                uint32_t sw = sw128((uint32_t)row * 128 + kg * 16);
                size_t src = (size_t)row * 1024 + k0 + kg * 8;
                cp_async16(sb + sw,          Ah + src);
                cp_async16(sb + OFF_AL + sw, Al + src);
                cp_async16(sb + OFF_BH + sw, Bh + src);
                cp_async16(sb + OFF_BL + sw, Bl + src);
            }
            cp_commit();
            cp_wait<1>();
        } else {
            cp_wait<0>();
        }
        __syncthreads();

        const uint32_t base = sbase + buf * BUFSZ;
        #pragma unroll
        for (int ks = 0; ks < 4; ks++) {
            const int kb = ks * 16;
            uint32_t ah[4][4], al[4][4], bh[4][2], bl[4][2];
            #pragma unroll
            for (int mt = 0; mt < 4; mt++) {
                uint32_t sw = sw128((uint32_t)(arow + mt * 16) * 128 + (acol8 + kb) * 2);
                ldsm_x4(ah[mt], base + sw);
                ldsm_x4(al[mt], base + OFF_AL + sw);
            }
            #pragma unroll
            for (int bt = 0; bt < 2; bt++) {
                uint32_t sw = sw128((uint32_t)(brow + bt * 16) * 128 + (bcol8 + kb) * 2);
                uint32_t t[4];
                ldsm_x4(t, base + OFF_BH + sw);
                bh[bt * 2][0] = t[0]; bh[bt * 2][1] = t[1];
                bh[bt * 2 + 1][0] = t[2]; bh[bt * 2 + 1][1] = t[3];
                ldsm_x4(t, base + OFF_BL + sw);
                bl[bt * 2][0] = t[0]; bl[bt * 2][1] = t[1];
                bl[bt * 2 + 1][0] = t[2]; bl[bt * 2 + 1][1] = t[3];
            }
            #pragma unroll
            for (int mt = 0; mt < 4; mt++)
                #pragma unroll
                for (int nt = 0; nt < 4; nt++) {
                    mma16816(c[mt][nt], ah[mt], bh[nt]);
                    mma16816(c[mt][nt], ah[mt], bl[nt]);
                    mma16816(c[mt][nt], al[mt], bh[nt]);
                }
        }
        __syncthreads();
        buf ^= 1;
    }

    const int r0 = lane >> 2, c0 = (lane & 3) * 2;
    #pragma unroll
    for (int mt = 0; mt < 4; mt++)
        #pragma unroll
        for (int nt = 0; nt < 4; nt++) {
            int row = wm * 64 + mt * 16 + r0;
            int col = wn * 32 + nt * 8 + c0;
            float2 v0 = make_float2(c[mt][nt][0] * 0.03125f, c[mt][nt][1] * 0.03125f);
            float2 v1 = make_float2(c[mt][nt][2] * 0.03125f, c[mt][nt][3] * 0.03125f);
            *(float2*)(Cg + (size_t)row * 1024 + col) = v0;
            *(float2*)(Cg + (size_t)(row + 8) * 1024 + col) = v1;
        }
}

// ---------------- K3: GEMM2 (single bf16) -> a2 row partials ----------------
// buf: Ah 16K + Bh 16K = 32K x2 = 64K.
static constexpr uint32_t OFF2_B = 16384;
static constexpr uint32_t BUFSZ2 = 32768;
static constexpr int GEMM2_SMEM = 65536;

__global__ void __launch_bounds__(256, 1)
gemm2_kernel()
{
    extern __shared__ unsigned char smem[];
    const uint32_t sbase = smem_u32(smem);
    const int tid  = threadIdx.x;
    const int wid  = tid >> 5, lane = tid & 31;
    const int q0   = blockIdx.x * 128;
    const int n0   = blockIdx.y * 128;     // d-slab
    const int b    = blockIdx.z;

    const __nv_bfloat16* Ah = g_Ph + ((size_t)b * Qn + q0) * Ln;
    const __nv_bfloat16* Bh = g_TNh + (size_t)b * Dn * Ln + (size_t)n0 * Ln;

    const int wm = wid >> 2, wn = wid & 3;
    const int arow  = wm * 64 + (lane & 7) + ((lane >> 3) & 1) * 8;
    const int acol8 = (lane >> 4) * 8;
    const int brow  = wn * 32 + (lane & 7) + (lane >> 4) * 8;
    const int bcol8 = ((lane >> 3) & 1) * 8;

    float c[4][4][4];
    #pragma unroll
    for (int mt = 0; mt < 4; mt++)
        #pragma unroll
        for (int nt = 0; nt < 4; nt++)
            #pragma unroll
            for (int i = 0; i < 4; i++) c[mt][nt][i] = 0.f;

    #pragma unroll
    for (int i = 0; i < 4; i++) {
        int g = tid + i * 256;
        int row = g >> 3, kg = g & 7;
        uint32_t sw = sw128((uint32_t)row * 128 + kg * 16);
        size_t src = (size_t)row * 1024 + kg * 8;
        cp_async16(sbase + sw,          Ah + src);
        cp_async16(sbase + OFF2_B + sw, Bh + src);
    }
    cp_commit();

    int buf = 0;
    for (int kc = 0; kc < 16; kc++) {
        if (kc + 1 < 16) {
            uint32_t sb = sbase + (buf ^ 1) * BUFSZ2;
            int k0 = (kc + 1) * 64;
            #pragma unroll
            for (int i = 0; i < 4; i++) {
                int g = tid + i * 256;
                int row = g >> 3, kg = g & 7;
                uint32_t sw = sw128((uint32_t)row * 128 + kg * 16);
                size_t src = (size_t)row * 1024 + k0 + kg * 8;
                cp_async16(sb + sw,          Ah + src);
                cp_async16(sb + OFF2_B + sw, Bh + src);
            }
            cp_commit();
            cp_wait<1>();
        } else {
            cp_wait<0>();
        }
        __syncthreads();

        const uint32_t base = sbase + buf * BUFSZ2;
        #pragma unroll
        for (int ks = 0; ks < 4; ks++) {
            const int kb = ks * 16;
            uint32_t ah[4][4], bh[4][2];
            #pragma unroll
            for (int mt = 0; mt < 4; mt++) {
                uint32_t sw = sw128((uint32_t)(arow + mt * 16) * 128 + (acol8 + kb) * 2);
                ldsm_x4(ah[mt], base + sw);
            }
            #pragma unroll
            for (int bt = 0; bt < 2; bt++) {
                uint32_t sw = sw128((uint32_t)(brow + bt * 16) * 128 + (bcol8 + kb) * 2);
                uint32_t t[4];
                ldsm_x4(t, base + OFF2_B + sw);
                bh[bt * 2][0] = t[0]; bh[bt * 2][1] = t[1];
                bh[bt * 2 + 1][0] = t[2]; bh[bt * 2 + 1][1] = t[3];
            }
            #pragma unroll
            for (int mt = 0; mt < 4; mt++)
                #pragma unroll
                for (int nt = 0; nt < 4; nt++)
                    mma16816(c[mt][nt], ah[mt], bh[nt]);
        }
        __syncthreads();
        buf ^= 1;
    }

    // ---- epilogue: per-row sum of squares, deterministic reduction ----
    float* red = (float*)smem;                 // [4][128] floats (aliases idle buf)
    const int r0 = lane >> 2;
    #pragma unroll
    for (int mt = 0; mt < 4; mt++) {
        float s0 = 0.f, s1 = 0.f;
        #pragma unroll
        for (int nt = 0; nt < 4; nt++) {
            s0 = fmaf(c[mt][nt][0], c[mt][nt][0], fmaf(c[mt][nt][1], c[mt][nt][1], s0));
            s1 = fmaf(c[mt][nt][2], c[mt][nt][2], fmaf(c[mt][nt][3], c[mt][nt][3], s1));
        }
        s0 += __shfl_xor_sync(0xffffffffu, s0, 1);
        s0 += __shfl_xor_sync(0xffffffffu, s0, 2);
        s1 += __shfl_xor_sync(0xffffffffu, s1, 1);
        s1 += __shfl_xor_sync(0xffffffffu, s1, 2);
        if ((lane & 3) == 0) {
            red[wn * 128 + wm * 64 + mt * 16 + r0]     = s0;
            red[wn * 128 + wm * 64 + mt * 16 + r0 + 8] = s1;
        }
    }
    __syncthreads();
    if (tid < 128) {
        float v = red[tid] + red[128 + tid] + red[256 + tid] + red[384 + tid];
        g_A2P[((size_t)b * 8 + blockIdx.y) * Qn + q0 + tid] = v;
    }
}

// ---------------- K4: final logits ------------------------------------------
__global__ void final_kernel(float* __restrict__ out) {
    const int idx = blockIdx.x * blockDim.x + threadIdx.x;   // row = b*512 + q
    const int b = idx >> 9, q = idx & 511;
    float a2 = 0.f;
    #pragma unroll
    for (int nt = 0; nt < 8; nt++)
        a2 += g_A2P[((size_t)b * 8 + nt) * Qn + q];
    float dn = fmaxf(g_QN[q], 1e-12f) * fmaxf(sqrtf(a2), 1e-12f);
    out[(size_t)q * Bn + b] = g_DOT[idx] / dn;
}

// ---------------- launch ----------------------------------------------------
extern "C" void kernel_launch(void* const* d_in, const int* in_sizes, int n_in,
                              void* d_out, int out_size)
{
    const float* queries = (const float*)d_in[0];   // [512,1024]
    const float* tokens  = (const float*)d_in[1];   // [64,1024,1024]
    float* out = (float*)d_out;                     // [512,64]

    cudaFuncSetAttribute(gemm1_kernel,
                         cudaFuncAttributeMaxDynamicSharedMemorySize, GEMM1_SMEM);
    cudaFuncSetAttribute(gemm2_kernel,
                         cudaFuncAttributeMaxDynamicSharedMemorySize, GEMM2_SMEM);

    convert_q_kernel<<<512, 256>>>(queries);                     // 512*1024/4/256
    qnorm_kernel<<<64, 256>>>(queries);
    convert_tk_kernel<<<65536, 256>>>(tokens);                   // 64M/4/256
    transpose_tn_kernel<<<dim3(Dn / 32, Ln / 64, Bn), 256>>>(tokens);
    gemm1_kernel<<<dim3(Qn / 128, Ln / 128, Bn), 256, GEMM1_SMEM>>>();
    softmax_kernel<<<Bn * Qn, 256>>>();
    gemm2_kernel<<<dim3(Qn / 128, Dn / 128, Bn), 256, GEMM2_SMEM>>>();
    final_kernel<<<(Bn * Qn) / 256, 256>>>(out);
}

// round 6
// speedup vs baseline: 5.5377x; 1.1096x over previous
#include <cuda_runtime.h>
#include <cuda_bf16.h>
#include <cstdint>
#include <math.h>

// SimilarityLogit on GB300 via mma.sync (HMMA) bf16 GEMMs.
//   queries      : [Q=512, D=1024]  fp32      (d_in[0])
//   local_tokens : [B=64, L=1024, D=1024] fp32 (d_in[1])
//   out          : [Q=512, B=64]   fp32  (out[q*64+b])
//
// Math: S = qT^t/32 ; P = softmax(S) ; agg = P T
//   out = dot(q,agg)/(max(||q||,eps) max(||agg||,eps))
// Identity: dot(q,agg) = 32 * sum_l P[l] S[l]  -> computed in softmax kernel.
// GEMM2 only supplies ||agg||^2 (error-tolerant -> single bf16, and its B
// operand is loaded directly from the [l][d] TKh layout via ldmatrix.trans,
// so no transposed token copy is needed).

static constexpr int Qn = 512, Dn = 1024, Ln = 1024, Bn = 64;

// ---------------- scratch (device globals; no runtime allocation) ----------
__device__ __nv_bfloat16 g_Qh[(size_t)Qn * Dn];
__device__ __nv_bfloat16 g_Ql[(size_t)Qn * Dn];
__device__ __nv_bfloat16 g_TKh[(size_t)Bn * Ln * Dn];
__device__ __nv_bfloat16 g_TKl[(size_t)Bn * Ln * Dn];
__device__ float         g_S[(size_t)Bn * Qn * Ln];
__device__ __nv_bfloat16 g_Ph[(size_t)Bn * Qn * Ln];
__device__ float         g_DOT[(size_t)Bn * Qn];
__device__ float         g_A2P[(size_t)Bn * 8 * Qn];   // per-(b, d-slab) row partials
__device__ float         g_QN[Qn];

// ---------------- PTX helpers ----------------------------------------------
__device__ __forceinline__ uint32_t smem_u32(const void* p) {
    uint32_t a;
    asm("{ .reg .u64 t; cvta.to.shared.u64 t, %1; cvt.u32.u64 %0, t; }"
        : "=r"(a) : "l"(p));
    return a;
}

__device__ __forceinline__ void cp_async16(uint32_t dst, const void* src) {
    asm volatile("cp.async.cg.shared.global [%0], [%1], 16;"
                 :: "r"(dst), "l"(src) : "memory");
}
__device__ __forceinline__ void cp_commit() {
    asm volatile("cp.async.commit_group;" ::: "memory");
}
template <int N>
__device__ __forceinline__ void cp_wait() {
    asm volatile("cp.async.wait_group %0;" :: "n"(N) : "memory");
}

__device__ __forceinline__ void ldsm_x4(uint32_t* r, uint32_t addr) {
    asm volatile("ldmatrix.sync.aligned.m8n8.x4.shared.b16 {%0,%1,%2,%3}, [%4];"
                 : "=r"(r[0]), "=r"(r[1]), "=r"(r[2]), "=r"(r[3]) : "r"(addr));
}

__device__ __forceinline__ void ldsm_x4_trans(uint32_t* r, uint32_t addr) {
    asm volatile("ldmatrix.sync.aligned.m8n8.x4.trans.shared.b16 {%0,%1,%2,%3}, [%4];"
                 : "=r"(r[0]), "=r"(r[1]), "=r"(r[2]), "=r"(r[3]) : "r"(addr));
}

__device__ __forceinline__ void mma16816(float* c, const uint32_t* a, const uint32_t* b) {
    asm volatile(
        "mma.sync.aligned.m16n8k16.row.col.f32.bf16.bf16.f32 "
        "{%0,%1,%2,%3}, {%4,%5,%6,%7}, {%8,%9}, {%0,%1,%2,%3};"
        : "+f"(c[0]), "+f"(c[1]), "+f"(c[2]), "+f"(c[3])
        : "r"(a[0]), "r"(a[1]), "r"(a[2]), "r"(a[3]), "r"(b[0]), "r"(b[1]));
}

__device__ __forceinline__ uint32_t sw128(uint32_t off) {
    return off ^ ((off >> 3) & 0x70);
}

__device__ __forceinline__ void split1(float x, __nv_bfloat16& h, __nv_bfloat16& l) {
    h = __float2bfloat16(x);
    l = __float2bfloat16(x - __bfloat162float(h));
}

// ---------------- K0a: convert queries (hi/lo) ------------------------------
__global__ void convert_q_kernel(const float* __restrict__ q) {
    int idx = blockIdx.x * blockDim.x + threadIdx.x;   // float4 index
    float4 v = ((const float4*)q)[idx];
    __nv_bfloat16 h[4], l[4];
    split1(v.x, h[0], l[0]); split1(v.y, h[1], l[1]);
    split1(v.z, h[2], l[2]); split1(v.w, h[3], l[3]);
    uint2 hp, lp;
    hp.x = (uint32_t)__bfloat16_as_ushort(h[0]) | ((uint32_t)__bfloat16_as_ushort(h[1]) << 16);
    hp.y = (uint32_t)__bfloat16_as_ushort(h[2]) | ((uint32_t)__bfloat16_as_ushort(h[3]) << 16);
    lp.x = (uint32_t)__bfloat16_as_ushort(l[0]) | ((uint32_t)__bfloat16_as_ushort(l[1]) << 16);
    lp.y = (uint32_t)__bfloat16_as_ushort(l[2]) | ((uint32_t)__bfloat16_as_ushort(l[3]) << 16);
    ((uint2*)g_Qh)[idx] = hp;
    ((uint2*)g_Ql)[idx] = lp;
}

// ---------------- K0b: query norms ------------------------------------------
__global__ void qnorm_kernel(const float* __restrict__ q) {
    const int warp = threadIdx.x >> 5, lane = threadIdx.x & 31;
    const int row = blockIdx.x * 8 + warp;
    const float4* qp = (const float4*)(q + (size_t)row * Dn);
    float s = 0.f;
    #pragma unroll
    for (int i = 0; i < 8; i++) {
        float4 v = qp[lane + i * 32];
        s = fmaf(v.x, v.x, fmaf(v.y, v.y, fmaf(v.z, v.z, fmaf(v.w, v.w, s))));
    }
    #pragma unroll
    for (int o = 16; o > 0; o >>= 1) s += __shfl_xor_sync(0xffffffffu, s, o);
    if (lane == 0) g_QN[row] = sqrtf(s);
}

// ---------------- K0c: convert tokens (hi/lo) -------------------------------
__global__ void convert_tk_kernel(const float* __restrict__ tok) {
    size_t idx = (size_t)blockIdx.x * blockDim.x + threadIdx.x;   // float4 index
    float4 v = ((const float4*)tok)[idx];
    __nv_bfloat16 h[4], l[4];
    split1(v.x, h[0], l[0]); split1(v.y, h[1], l[1]);
    split1(v.z, h[2], l[2]); split1(v.w, h[3], l[3]);
    uint2 hp, lp;
    hp.x = (uint32_t)__bfloat16_as_ushort(h[0]) | ((uint32_t)__bfloat16_as_ushort(h[1]) << 16);
    hp.y = (uint32_t)__bfloat16_as_ushort(h[2]) | ((uint32_t)__bfloat16_as_ushort(h[3]) << 16);
    lp.x = (uint32_t)__bfloat16_as_ushort(l[0]) | ((uint32_t)__bfloat16_as_ushort(l[1]) << 16);
    lp.y = (uint32_t)__bfloat16_as_ushort(l[2]) | ((uint32_t)__bfloat16_as_ushort(l[3]) << 16);
    ((uint2*)g_TKh)[idx] = hp;
    ((uint2*)g_TKl)[idx] = lp;
}

// ---------------- K2: warp-per-row softmax + dot + split P ------------------
__global__ void softmax_kernel() {
    const int warp = threadIdx.x >> 5, lane = threadIdx.x & 31;
    const int row = blockIdx.x * 8 + warp;             // = b*Qn + q
    const float4* srow = (const float4*)(g_S + (size_t)row * Ln);

    float4 v[8];
    #pragma unroll
    for (int i = 0; i < 8; i++) v[i] = srow[lane + i * 32];

    float m = -INFINITY;
    #pragma unroll
    for (int i = 0; i < 8; i++)
        m = fmaxf(m, fmaxf(fmaxf(v[i].x, v[i].y), fmaxf(v[i].z, v[i].w)));
    #pragma unroll
    for (int o = 16; o > 0; o >>= 1) m = fmaxf(m, __shfl_xor_sync(0xffffffffu, m, o));

    float s = 0.f, ev = 0.f;
    float4 e[8];
    #pragma unroll
    for (int i = 0; i < 8; i++) {
        e[i].x = expf(v[i].x - m); e[i].y = expf(v[i].y - m);
        e[i].z = expf(v[i].z - m); e[i].w = expf(v[i].w - m);
        s  += e[i].x + e[i].y + e[i].z + e[i].w;
        ev += e[i].x * v[i].x + e[i].y * v[i].y + e[i].z * v[i].z + e[i].w * v[i].w;
    }
    #pragma unroll
    for (int o = 16; o > 0; o >>= 1) {
        s  += __shfl_xor_sync(0xffffffffu, s, o);
        ev += __shfl_xor_sync(0xffffffffu, ev, o);
    }
    const float inv = 1.0f / s;
    if (lane == 0) g_DOT[row] = 32.0f * inv * ev;      // dot(q, agg), exact identity

    uint2* pout = (uint2*)(g_Ph + (size_t)row * Ln);
    #pragma unroll
    for (int i = 0; i < 8; i++) {
        __nv_bfloat16 h0 = __float2bfloat16(e[i].x * inv);
        __nv_bfloat16 h1 = __float2bfloat16(e[i].y * inv);
        __nv_bfloat16 h2 = __float2bfloat16(e[i].z * inv);
        __nv_bfloat16 h3 = __float2bfloat16(e[i].w * inv);
        uint2 hp;
        hp.x = (uint32_t)__bfloat16_as_ushort(h0) | ((uint32_t)__bfloat16_as_ushort(h1) << 16);
        hp.y = (uint32_t)__bfloat16_as_ushort(h2) | ((uint32_t)__bfloat16_as_ushort(h3) << 16);
        pout[lane + i * 32] = hp;
    }
}

// ---------------- K1: GEMM1 (3-term split) ----------------------------------
// CTA tile 128x128, K chunks of 64. buf: Ah Al Bh Bl (16K each) x2 = 128K.
static constexpr uint32_t OFF_AL = 16384;
static constexpr uint32_t OFF_BH = 32768;
static constexpr uint32_t OFF_BL = 49152;
static constexpr uint32_t BUFSZ  = 65536;
static constexpr int GEMM1_SMEM = 131072;

__global__ void __launch_bounds__(256, 1)
gemm1_kernel()
{
    extern __shared__ unsigned char smem[];
    const uint32_t sbase = smem_u32(smem);
    const int tid  = threadIdx.x;
    const int wid  = tid >> 5, lane = tid & 31;
    const int q0   = blockIdx.x * 128;
    const int n0   = blockIdx.y * 128;
    const int b    = blockIdx.z;

    const __nv_bfloat16* Ah = g_Qh + (size_t)q0 * Dn;
    const __nv_bfloat16* Al = g_Ql + (size_t)q0 * Dn;
    const __nv_bfloat16* Bh = g_TKh + (size_t)b * Ln * Dn + (size_t)n0 * Dn;
    const __nv_bfloat16* Bl = g_TKl + (size_t)b * Ln * Dn + (size_t)n0 * Dn;
    float* Cg = g_S + ((size_t)b * Qn + q0) * Ln + n0;

    const int wm = wid >> 2, wn = wid & 3;
    const int arow  = wm * 64 + (lane & 7) + ((lane >> 3) & 1) * 8;
    const int acol8 = (lane >> 4) * 8;
    const int brow  = wn * 32 + (lane & 7) + (lane >> 4) * 8;
    const int bcol8 = ((lane >> 3) & 1) * 8;

    float c[4][4][4];
    #pragma unroll
    for (int mt = 0; mt < 4; mt++)
        #pragma unroll
        for (int nt = 0; nt < 4; nt++)
            #pragma unroll
            for (int i = 0; i < 4; i++) c[mt][nt][i] = 0.f;

    #pragma unroll
    for (int i = 0; i < 4; i++) {
        int g = tid + i * 256;
        int row = g >> 3, kg = g & 7;
        uint32_t sw = sw128((uint32_t)row * 128 + kg * 16);
        size_t src = (size_t)row * 1024 + kg * 8;
        cp_async16(sbase + sw,          Ah + src);
        cp_async16(sbase + OFF_AL + sw, Al + src);
        cp_async16(sbase + OFF_BH + sw, Bh + src);
        cp_async16(sbase + OFF_BL + sw, Bl + src);
    }
    cp_commit();

    int buf = 0;
    for (int kc = 0; kc < 16; kc++) {
        if (kc + 1 < 16) {
            uint32_t sb = sbase + (buf ^ 1) * BUFSZ;
            int k0 = (kc + 1) * 64;
            #pragma unroll
            for (int i = 0; i < 4; i++) {
                int g = tid + i * 256;
                int row = g >> 3, kg = g & 7;
                uint32_t sw = sw128((uint32_t)row * 128 + kg * 16);
                size_t src = (size_t)row * 1024 + k0 + kg * 8;
                cp_async16(sb + sw,          Ah + src);
                cp_async16(sb + OFF_AL + sw, Al + src);
                cp_async16(sb + OFF_BH + sw, Bh + src);
                cp_async16(sb + OFF_BL + sw, Bl + src);
            }
            cp_commit();
            cp_wait<1>();
        } else {
            cp_wait<0>();
        }
        __syncthreads();

        const uint32_t base = sbase + buf * BUFSZ;
        #pragma unroll
        for (int ks = 0; ks < 4; ks++) {
            const int kb = ks * 16;
            uint32_t ah[4][4], al[4][4], bh[4][2], bl[4][2];
            #pragma unroll
            for (int mt = 0; mt < 4; mt++) {
                uint32_t sw = sw128((uint32_t)(arow + mt * 16) * 128 + (acol8 + kb) * 2);
                ldsm_x4(ah[mt], base + sw);
                ldsm_x4(al[mt], base + OFF_AL + sw);
            }
            #pragma unroll
            for (int bt = 0; bt < 2; bt++) {
                uint32_t sw = sw128((uint32_t)(brow + bt * 16) * 128 + (bcol8 + kb) * 2);
                uint32_t t[4];
                ldsm_x4(t, base + OFF_BH + sw);
                bh[bt * 2][0] = t[0]; bh[bt * 2][1] = t[1];
                bh[bt * 2 + 1][0] = t[2]; bh[bt * 2 + 1][1] = t[3];
                ldsm_x4(t, base + OFF_BL + sw);
                bl[bt * 2][0] = t[0]; bl[bt * 2][1] = t[1];
                bl[bt * 2 + 1][0] = t[2]; bl[bt * 2 + 1][1] = t[3];
            }
            #pragma unroll
            for (int mt = 0; mt < 4; mt++)
                #pragma unroll
                for (int nt = 0; nt < 4; nt++) {
                    mma16816(c[mt][nt], ah[mt], bh[nt]);
                    mma16816(c[mt][nt], ah[mt], bl[nt]);
                    mma16816(c[mt][nt], al[mt], bh[nt]);
                }
        }
        __syncthreads();
        buf ^= 1;
    }

    const int r0 = lane >> 2, c0 = (lane & 3) * 2;
    #pragma unroll
    for (int mt = 0; mt < 4; mt++)
        #pragma unroll
        for (int nt = 0; nt < 4; nt++) {
            int row = wm * 64 + mt * 16 + r0;
            int col = wn * 32 + nt * 8 + c0;
            float2 v0 = make_float2(c[mt][nt][0] * 0.03125f, c[mt][nt][1] * 0.03125f);
            float2 v1 = make_float2(c[mt][nt][2] * 0.03125f, c[mt][nt][3] * 0.03125f);
            *(float2*)(Cg + (size_t)row * 1024 + col) = v0;
            *(float2*)(Cg + (size_t)(row + 8) * 1024 + col) = v1;
        }
}

// ---------------- K3: GEMM2 (single bf16, B via ldmatrix.trans) -------------
// A tile: Ph 128(q) x 64(l), K-major, 16K. B tile: TKh 64(l) x 128(d), 16K.
// B smem layout: row = l (64 rows x 256B), 16B granule g in row: swizzled
//   (g&7) ^ (row&7) within each 128B half -> conflict-free trans-ldmatrix.
static constexpr uint32_t OFF2_B = 16384;
static constexpr uint32_t BUFSZ2 = 32768;
static constexpr int GEMM2_SMEM = 65536;

__device__ __forceinline__ uint32_t swB(uint32_t row, uint32_t nbyte) {
    uint32_t g = nbyte >> 4;
    uint32_t g7 = (g & 7) ^ (row & 7);
    return row * 256 + (g & 8) * 16 + g7 * 16;
}

__global__ void __launch_bounds__(256, 1)
gemm2_kernel()
{
    extern __shared__ unsigned char smem[];
    const uint32_t sbase = smem_u32(smem);
    const int tid  = threadIdx.x;
    const int wid  = tid >> 5, lane = tid & 31;
    const int q0   = blockIdx.x * 128;
    const int n0   = blockIdx.y * 128;     // d-slab
    const int b    = blockIdx.z;

    const __nv_bfloat16* Ah = g_Ph + ((size_t)b * Qn + q0) * Ln;
    const __nv_bfloat16* Bh = g_TKh + (size_t)b * Ln * Dn;   // [l][d]

    const int wm = wid >> 2, wn = wid & 3;
    const int arow  = wm * 64 + (lane & 7) + ((lane >> 3) & 1) * 8;
    const int acol8 = (lane >> 4) * 8;

    // trans-ldmatrix lane addressing: lane L -> mat L>>3, r = L&7
    const int t_r    = lane & 7;
    const int t_krow = ((lane >> 3) & 1) * 8 + t_r;     // +8 for mats 1,3
    const int t_nb   = (lane >> 4) * 16;                // +16B for mats 2,3

    float c[4][4][4];
    #pragma unroll
    for (int mt = 0; mt < 4; mt++)
        #pragma unroll
        for (int nt = 0; nt < 4; nt++)
            #pragma unroll
            for (int i = 0; i < 4; i++) c[mt][nt][i] = 0.f;

    // stage chunk 0: A 1024 granules, B 1024 granules -> 8 cp.async / thread
    #pragma unroll
    for (int i = 0; i < 4; i++) {
        int g = tid + i * 256;
        {   // A: 128 rows x 8 granules
            int row = g >> 3, kg = g & 7;
            uint32_t sw = sw128((uint32_t)row * 128 + kg * 16);
            cp_async16(sbase + sw, Ah + (size_t)row * 1024 + kg * 8);
        }
        {   // B: 64 rows x 16 granules
            int row = g >> 4, kg = g & 15;
            cp_async16(sbase + OFF2_B + swB(row, kg * 16),
                       Bh + (size_t)row * 1024 + n0 + kg * 8);
        }
    }
    cp_commit();

    int buf = 0;
    for (int kc = 0; kc < 16; kc++) {
        if (kc + 1 < 16) {
            uint32_t sb = sbase + (buf ^ 1) * BUFSZ2;
            int k0 = (kc + 1) * 64;
            #pragma unroll
            for (int i = 0; i < 4; i++) {
                int g = tid + i * 256;
                {
                    int row = g >> 3, kg = g & 7;
                    uint32_t sw = sw128((uint32_t)row * 128 + kg * 16);
                    cp_async16(sb + sw, Ah + (size_t)row * 1024 + k0 + kg * 8);
                }
                {
                    int row = g >> 4, kg = g & 15;
                    cp_async16(sb + OFF2_B + swB(row, kg * 16),
                               Bh + (size_t)(k0 + row) * 1024 + n0 + kg * 8);
                }
            }
            cp_commit();
            cp_wait<1>();
        } else {
            cp_wait<0>();
        }
        __syncthreads();

        const uint32_t base = sbase + buf * BUFSZ2;
        #pragma unroll
        for (int ks = 0; ks < 4; ks++) {
            const int kb = ks * 16;
            uint32_t ah[4][4], bh[4][2];
            #pragma unroll
            for (int mt = 0; mt < 4; mt++) {
                uint32_t sw = sw128((uint32_t)(arow + mt * 16) * 128 + (acol8 + kb) * 2);
                ldsm_x4(ah[mt], base + sw);
            }
            #pragma unroll
            for (int bt = 0; bt < 2; bt++) {
                // mats: (k kb..+7, n+0..7), (k kb+8..+15, n+0..7), (+8n), (+8n,+8k)
                uint32_t row = kb + t_krow;
                uint32_t nb  = (wn * 32 + bt * 16) * 2 + t_nb;
                uint32_t t[4];
                ldsm_x4_trans(t, base + OFF2_B + swB(row, nb));
                bh[bt * 2][0] = t[0]; bh[bt * 2][1] = t[1];
                bh[bt * 2 + 1][0] = t[2]; bh[bt * 2 + 1][1] = t[3];
            }
            #pragma unroll
            for (int mt = 0; mt < 4; mt++)
                #pragma unroll
                for (int nt = 0; nt < 4; nt++)
                    mma16816(c[mt][nt], ah[mt], bh[nt]);
        }
        __syncthreads();
        buf ^= 1;
    }

    // ---- epilogue: per-row sum of squares, deterministic reduction ----
    float* red = (float*)smem;                 // aliases staging (done with it)
    const int r0 = lane >> 2;
    #pragma unroll
    for (int mt = 0; mt < 4; mt++) {
        float s0 = 0.f, s1 = 0.f;
        #pragma unroll
        for (int nt = 0; nt < 4; nt++) {
            s0 = fmaf(c[mt][nt][0], c[mt][nt][0], fmaf(c[mt][nt][1], c[mt][nt][1], s0));
            s1 = fmaf(c[mt][nt][2], c[mt][nt][2], fmaf(c[mt][nt][3], c[mt][nt][3], s1));
        }
        s0 += __shfl_xor_sync(0xffffffffu, s0, 1);
        s0 += __shfl_xor_sync(0xffffffffu, s0, 2);
        s1 += __shfl_xor_sync(0xffffffffu, s1, 1);
        s1 += __shfl_xor_sync(0xffffffffu, s1, 2);
        if ((lane & 3) == 0) {
            red[wn * 128 + wm * 64 + mt * 16 + r0]     = s0;
            red[wn * 128 + wm * 64 + mt * 16 + r0 + 8] = s1;
        }
    }
    __syncthreads();
    if (tid < 128) {
        float v = red[tid] + red[128 + tid] + red[256 + tid] + red[384 + tid];
        g_A2P[((size_t)b * 8 + blockIdx.y) * Qn + q0 + tid] = v;
    }
}

// ---------------- K4: final logits ------------------------------------------
__global__ void final_kernel(float* __restrict__ out) {
    const int idx = blockIdx.x * blockDim.x + threadIdx.x;   // row = b*512 + q
    const int b = idx >> 9, q = idx & 511;
    float a2 = 0.f;
    #pragma unroll
    for (int nt = 0; nt < 8; nt++)
        a2 += g_A2P[((size_t)b * 8 + nt) * Qn + q];
    float dn = fmaxf(g_QN[q], 1e-12f) * fmaxf(sqrtf(a2), 1e-12f);
    out[(size_t)q * Bn + b] = g_DOT[idx] / dn;
}

// ---------------- launch ----------------------------------------------------
extern "C" void kernel_launch(void* const* d_in, const int* in_sizes, int n_in,
                              void* d_out, int out_size)
{
    const float* queries = (const float*)d_in[0];   // [512,1024]
    const float* tokens  = (const float*)d_in[1];   // [64,1024,1024]
    float* out = (float*)d_out;                     // [512,64]

    cudaFuncSetAttribute(gemm1_kernel,
                         cudaFuncAttributeMaxDynamicSharedMemorySize, GEMM1_SMEM);
    cudaFuncSetAttribute(gemm2_kernel,
                         cudaFuncAttributeMaxDynamicSharedMemorySize, GEMM2_SMEM);

    convert_q_kernel<<<512, 256>>>(queries);
    qnorm_kernel<<<64, 256>>>(queries);
    convert_tk_kernel<<<65536, 256>>>(tokens);
    gemm1_kernel<<<dim3(Qn / 128, Ln / 128, Bn), 256, GEMM1_SMEM>>>();
    softmax_kernel<<<Bn * Qn / 8, 256>>>();
    gemm2_kernel<<<dim3(Qn / 128, Dn / 128, Bn), 256, GEMM2_SMEM>>>();
    final_kernel<<<(Bn * Qn) / 256, 256>>>(out);
}

// round 7
// speedup vs baseline: 6.8149x; 1.2306x over previous
#include <cuda_runtime.h>
#include <cuda_fp16.h>
#include <cstdint>
#include <math.h>

// SimilarityLogit on GB300 via mma.sync (HMMA) fp16 GEMMs, fp32 accumulate.
//   queries      : [Q=512, D=1024]  fp32      (d_in[0])
//   local_tokens : [B=64, L=1024, D=1024] fp32 (d_in[1])
//   out          : [Q=512, B=64]   fp32  (out[q*64+b])
//
// Math: S = qT^t/32 ; P = softmax(S) ; agg = P T
//   out = dot(q,agg)/(max(||q||,eps) max(||agg||,eps))
// Identity: dot(q,agg) = 32 * sum_l P[l] S[l]  -> computed in softmax kernel.
// GEMM2 only supplies ||agg||^2 (error-tolerant). Tokens are stored ONCE as
// fp16 [l][d]; GEMM1 uses them K-major, GEMM2 loads its B fragments from the
// same layout via ldmatrix.trans. Queries are split fp16 hi/lo (2-term GEMM1).

static constexpr int Qn = 512, Dn = 1024, Ln = 1024, Bn = 64;

// ---------------- scratch (device globals; no runtime allocation) ----------
__device__ __half g_Qh[(size_t)Qn * Dn];
__device__ __half g_Ql[(size_t)Qn * Dn];
__device__ __half g_TH[(size_t)Bn * Ln * Dn];          // tokens fp16 [b][l][d]
__device__ float  g_S[(size_t)Bn * Qn * Ln];
__device__ __half g_Ph[(size_t)Bn * Qn * Ln];
__device__ float  g_DOT[(size_t)Bn * Qn];
__device__ float  g_A2P[(size_t)Bn * 8 * Qn];          // per-(b, d-slab) row partials
__device__ float  g_QN[Qn];

// ---------------- PTX helpers ----------------------------------------------
__device__ __forceinline__ uint32_t smem_u32(const void* p) {
    uint32_t a;
    asm("{ .reg .u64 t; cvta.to.shared.u64 t, %1; cvt.u32.u64 %0, t; }"
        : "=r"(a) : "l"(p));
    return a;
}

__device__ __forceinline__ void cp_async16(uint32_t dst, const void* src) {
    asm volatile("cp.async.cg.shared.global [%0], [%1], 16;"
                 :: "r"(dst), "l"(src) : "memory");
}
__device__ __forceinline__ void cp_commit() {
    asm volatile("cp.async.commit_group;" ::: "memory");
}
template <int N>
__device__ __forceinline__ void cp_wait() {
    asm volatile("cp.async.wait_group %0;" :: "n"(N) : "memory");
}

__device__ __forceinline__ void ldsm_x4(uint32_t* r, uint32_t addr) {
    asm volatile("ldmatrix.sync.aligned.m8n8.x4.shared.b16 {%0,%1,%2,%3}, [%4];"
                 : "=r"(r[0]), "=r"(r[1]), "=r"(r[2]), "=r"(r[3]) : "r"(addr));
}

__device__ __forceinline__ void ldsm_x4_trans(uint32_t* r, uint32_t addr) {
    asm volatile("ldmatrix.sync.aligned.m8n8.x4.trans.shared.b16 {%0,%1,%2,%3}, [%4];"
                 : "=r"(r[0]), "=r"(r[1]), "=r"(r[2]), "=r"(r[3]) : "r"(addr));
}

__device__ __forceinline__ void mma16816(float* c, const uint32_t* a, const uint32_t* b) {
    asm volatile(
        "mma.sync.aligned.m16n8k16.row.col.f32.f16.f16.f32 "
        "{%0,%1,%2,%3}, {%4,%5,%6,%7}, {%8,%9}, {%0,%1,%2,%3};"
        : "+f"(c[0]), "+f"(c[1]), "+f"(c[2]), "+f"(c[3])
        : "r"(a[0]), "r"(a[1]), "r"(a[2]), "r"(a[3]), "r"(b[0]), "r"(b[1]));
}

__device__ __forceinline__ uint32_t sw128(uint32_t off) {
    return off ^ ((off >> 3) & 0x70);
}

// ---------------- K0a: convert queries (fp16 hi/lo) -------------------------
__global__ void convert_q_kernel(const float* __restrict__ q) {
    int idx = blockIdx.x * blockDim.x + threadIdx.x;   // float4 index
    float4 v = ((const float4*)q)[idx];
    __half h[4], l[4];
    #pragma unroll
    for (int i = 0; i < 4; i++) {
        float x = (&v.x)[i];
        h[i] = __float2half(x);
        l[i] = __float2half(x - __half2float(h[i]));
    }
    uint2 hp, lp;
    hp.x = (uint32_t)__half_as_ushort(h[0]) | ((uint32_t)__half_as_ushort(h[1]) << 16);
    hp.y = (uint32_t)__half_as_ushort(h[2]) | ((uint32_t)__half_as_ushort(h[3]) << 16);
    lp.x = (uint32_t)__half_as_ushort(l[0]) | ((uint32_t)__half_as_ushort(l[1]) << 16);
    lp.y = (uint32_t)__half_as_ushort(l[2]) | ((uint32_t)__half_as_ushort(l[3]) << 16);
    ((uint2*)g_Qh)[idx] = hp;
    ((uint2*)g_Ql)[idx] = lp;
}

// ---------------- K0b: query norms ------------------------------------------
__global__ void qnorm_kernel(const float* __restrict__ q) {
    const int warp = threadIdx.x >> 5, lane = threadIdx.x & 31;
    const int row = blockIdx.x * 8 + warp;
    const float4* qp = (const float4*)(q + (size_t)row * Dn);
    float s = 0.f;
    #pragma unroll
    for (int i = 0; i < 8; i++) {
        float4 v = qp[lane + i * 32];
        s = fmaf(v.x, v.x, fmaf(v.y, v.y, fmaf(v.z, v.z, fmaf(v.w, v.w, s))));
    }
    #pragma unroll
    for (int o = 16; o > 0; o >>= 1) s += __shfl_xor_sync(0xffffffffu, s, o);
    if (lane == 0) g_QN[row] = sqrtf(s);
}

// ---------------- K0c: convert tokens (single fp16) -------------------------
__global__ void convert_tk_kernel(const float* __restrict__ tok) {
    size_t idx = (size_t)blockIdx.x * blockDim.x + threadIdx.x;   // float4 index
    float4 v = ((const float4*)tok)[idx];
    uint2 hp;
    __half h0 = __float2half(v.x), h1 = __float2half(v.y);
    __half h2 = __float2half(v.z), h3 = __float2half(v.w);
    hp.x = (uint32_t)__half_as_ushort(h0) | ((uint32_t)__half_as_ushort(h1) << 16);
    hp.y = (uint32_t)__half_as_ushort(h2) | ((uint32_t)__half_as_ushort(h3) << 16);
    ((uint2*)g_TH)[idx] = hp;
}

// ---------------- K2: warp-per-row softmax + dot + fp16 P -------------------
__global__ void softmax_kernel() {
    const int warp = threadIdx.x >> 5, lane = threadIdx.x & 31;
    const int row = blockIdx.x * 8 + warp;             // = b*Qn + q
    const float4* srow = (const float4*)(g_S + (size_t)row * Ln);

    float4 v[8];
    #pragma unroll
    for (int i = 0; i < 8; i++) v[i] = srow[lane + i * 32];

    float m = -INFINITY;
    #pragma unroll
    for (int i = 0; i < 8; i++)
        m = fmaxf(m, fmaxf(fmaxf(v[i].x, v[i].y), fmaxf(v[i].z, v[i].w)));
    #pragma unroll
    for (int o = 16; o > 0; o >>= 1) m = fmaxf(m, __shfl_xor_sync(0xffffffffu, m, o));

    float s = 0.f, ev = 0.f;
    float4 e[8];
    #pragma unroll
    for (int i = 0; i < 8; i++) {
        e[i].x = expf(v[i].x - m); e[i].y = expf(v[i].y - m);
        e[i].z = expf(v[i].z - m); e[i].w = expf(v[i].w - m);
        s  += e[i].x + e[i].y + e[i].z + e[i].w;
        ev += e[i].x * v[i].x + e[i].y * v[i].y + e[i].z * v[i].z + e[i].w * v[i].w;
    }
    #pragma unroll
    for (int o = 16; o > 0; o >>= 1) {
        s  += __shfl_xor_sync(0xffffffffu, s, o);
        ev += __shfl_xor_sync(0xffffffffu, ev, o);
    }
    const float inv = 1.0f / s;
    if (lane == 0) g_DOT[row] = 32.0f * inv * ev;      // dot(q, agg), exact identity

    uint2* pout = (uint2*)(g_Ph + (size_t)row * Ln);
    #pragma unroll
    for (int i = 0; i < 8; i++) {
        __half h0 = __float2half(e[i].x * inv);
        __half h1 = __float2half(e[i].y * inv);
        __half h2 = __float2half(e[i].z * inv);
        __half h3 = __float2half(e[i].w * inv);
        uint2 hp;
        hp.x = (uint32_t)__half_as_ushort(h0) | ((uint32_t)__half_as_ushort(h1) << 16);
        hp.y = (uint32_t)__half_as_ushort(h2) | ((uint32_t)__half_as_ushort(h3) << 16);
        pout[lane + i * 32] = hp;
    }
}

// ---------------- K1: GEMM1 (2-term: Qh.T + Ql.T) ---------------------------
// CTA tile 128x128, K chunks of 64. buf: Ah Al Bh (16K each) x2 = 96K.
static constexpr uint32_t OFF_AL = 16384;
static constexpr uint32_t OFF_BH = 32768;
static constexpr uint32_t BUFSZ  = 49152;
static constexpr int GEMM1_SMEM = 98304;

__global__ void __launch_bounds__(256, 1)
gemm1_kernel()
{
    extern __shared__ unsigned char smem[];
    const uint32_t sbase = smem_u32(smem);
    const int tid  = threadIdx.x;
    const int wid  = tid >> 5, lane = tid & 31;
    const int q0   = blockIdx.x * 128;
    const int n0   = blockIdx.y * 128;
    const int b    = blockIdx.z;

    const __half* Ah = g_Qh + (size_t)q0 * Dn;
    const __half* Al = g_Ql + (size_t)q0 * Dn;
    const __half* Bh = g_TH + (size_t)b * Ln * Dn + (size_t)n0 * Dn;
    float* Cg = g_S + ((size_t)b * Qn + q0) * Ln + n0;

    const int wm = wid >> 2, wn = wid & 3;
    const int arow  = wm * 64 + (lane & 7) + ((lane >> 3) & 1) * 8;
    const int acol8 = (lane >> 4) * 8;
    const int brow  = wn * 32 + (lane & 7) + (lane >> 4) * 8;
    const int bcol8 = ((lane >> 3) & 1) * 8;

    float c[4][4][4];
    #pragma unroll
    for (int mt = 0; mt < 4; mt++)
        #pragma unroll
        for (int nt = 0; nt < 4; nt++)
            #pragma unroll
            for (int i = 0; i < 4; i++) c[mt][nt][i] = 0.f;

    #pragma unroll
    for (int i = 0; i < 4; i++) {
        int g = tid + i * 256;
        int row = g >> 3, kg = g & 7;
        uint32_t sw = sw128((uint32_t)row * 128 + kg * 16);
        size_t src = (size_t)row * 1024 + kg * 8;
        cp_async16(sbase + sw,          Ah + src);
        cp_async16(sbase + OFF_AL + sw, Al + src);
        cp_async16(sbase + OFF_BH + sw, Bh + src);
    }
    cp_commit();

    int buf = 0;
    for (int kc = 0; kc < 16; kc++) {
        if (kc + 1 < 16) {
            uint32_t sb = sbase + (buf ^ 1) * BUFSZ;
            int k0 = (kc + 1) * 64;
            #pragma unroll
            for (int i = 0; i < 4; i++) {
                int g = tid + i * 256;
                int row = g >> 3, kg = g & 7;
                uint32_t sw = sw128((uint32_t)row * 128 + kg * 16);
                size_t src = (size_t)row * 1024 + k0 + kg * 8;
                cp_async16(sb + sw,          Ah + src);
                cp_async16(sb + OFF_AL + sw, Al + src);
                cp_async16(sb + OFF_BH + sw, Bh + src);
            }
            cp_commit();
            cp_wait<1>();
        } else {
            cp_wait<0>();
        }
        __syncthreads();

        const uint32_t base = sbase + buf * BUFSZ;
        #pragma unroll
        for (int ks = 0; ks < 4; ks++) {
            const int kb = ks * 16;
            uint32_t ah[4][4], al[4][4], bh[4][2];
            #pragma unroll
            for (int mt = 0; mt < 4; mt++) {
                uint32_t sw = sw128((uint32_t)(arow + mt * 16) * 128 + (acol8 + kb) * 2);
                ldsm_x4(ah[mt], base + sw);
                ldsm_x4(al[mt], base + OFF_AL + sw);
            }
            #pragma unroll
            for (int bt = 0; bt < 2; bt++) {
                uint32_t sw = sw128((uint32_t)(brow + bt * 16) * 128 + (bcol8 + kb) * 2);
                uint32_t t[4];
                ldsm_x4(t, base + OFF_BH + sw);
                bh[bt * 2][0] = t[0]; bh[bt * 2][1] = t[1];
                bh[bt * 2 + 1][0] = t[2]; bh[bt * 2 + 1][1] = t[3];
            }
            #pragma unroll
            for (int mt = 0; mt < 4; mt++)
                #pragma unroll
                for (int nt = 0; nt < 4; nt++) {
                    mma16816(c[mt][nt], ah[mt], bh[nt]);
                    mma16816(c[mt][nt], al[mt], bh[nt]);
                }
        }
        __syncthreads();
        buf ^= 1;
    }

    const int r0 = lane >> 2, c0 = (lane & 3) * 2;
    #pragma unroll
    for (int mt = 0; mt < 4; mt++)
        #pragma unroll
        for (int nt = 0; nt < 4; nt++) {
            int row = wm * 64 + mt * 16 + r0;
            int col = wn * 32 + nt * 8 + c0;
            float2 v0 = make_float2(c[mt][nt][0] * 0.03125f, c[mt][nt][1] * 0.03125f);
            float2 v1 = make_float2(c[mt][nt][2] * 0.03125f, c[mt][nt][3] * 0.03125f);
            *(float2*)(Cg + (size_t)row * 1024 + col) = v0;
            *(float2*)(Cg + (size_t)(row + 8) * 1024 + col) = v1;
        }
}

// ---------------- K3: GEMM2 (fp16, B via ldmatrix.trans) --------------------
// A tile: Ph 128(q) x 64(l), K-major, 16K. B tile: TH 64(l) x 128(d), 16K.
// B smem layout: row = l (64 rows x 256B), 16B granule g in row: swizzled
//   (g&7) ^ (row&7) within each 128B half -> conflict-free trans-ldmatrix.
static constexpr uint32_t OFF2_B = 16384;
static constexpr uint32_t BUFSZ2 = 32768;
static constexpr int GEMM2_SMEM = 65536;

__device__ __forceinline__ uint32_t swB(uint32_t row, uint32_t nbyte) {
    uint32_t g = nbyte >> 4;
    uint32_t g7 = (g & 7) ^ (row & 7);
    return row * 256 + (g & 8) * 16 + g7 * 16;
}

__global__ void __launch_bounds__(256, 1)
gemm2_kernel()
{
    extern __shared__ unsigned char smem[];
    const uint32_t sbase = smem_u32(smem);
    const int tid  = threadIdx.x;
    const int wid  = tid >> 5, lane = tid & 31;
    const int q0   = blockIdx.x * 128;
    const int n0   = blockIdx.y * 128;     // d-slab
    const int b    = blockIdx.z;

    const __half* Ah = g_Ph + ((size_t)b * Qn + q0) * Ln;
    const __half* Bh = g_TH + (size_t)b * Ln * Dn;   // [l][d]

    const int wm = wid >> 2, wn = wid & 3;
    const int arow  = wm * 64 + (lane & 7) + ((lane >> 3) & 1) * 8;
    const int acol8 = (lane >> 4) * 8;

    const int t_r    = lane & 7;
    const int t_krow = ((lane >> 3) & 1) * 8 + t_r;
    const int t_nb   = (lane >> 4) * 16;

    float c[4][4][4];
    #pragma unroll
    for (int mt = 0; mt < 4; mt++)
        #pragma unroll
        for (int nt = 0; nt < 4; nt++)
            #pragma unroll
            for (int i = 0; i < 4; i++) c[mt][nt][i] = 0.f;

    #pragma unroll
    for (int i = 0; i < 4; i++) {
        int g = tid + i * 256;
        {   // A: 128 rows x 8 granules
            int row = g >> 3, kg = g & 7;
            uint32_t sw = sw128((uint32_t)row * 128 + kg * 16);
            cp_async16(sbase + sw, Ah + (size_t)row * 1024 + kg * 8);
        }
        {   // B: 64 rows x 16 granules
            int row = g >> 4, kg = g & 15;
            cp_async16(sbase + OFF2_B + swB(row, kg * 16),
                       Bh + (size_t)row * 1024 + n0 + kg * 8);
        }
    }
    cp_commit();

    int buf = 0;
    for (int kc = 0; kc < 16; kc++) {
        if (kc + 1 < 16) {
            uint32_t sb = sbase + (buf ^ 1) * BUFSZ2;
            int k0 = (kc + 1) * 64;
            #pragma unroll
            for (int i = 0; i < 4; i++) {
                int g = tid + i * 256;
                {
                    int row = g >> 3, kg = g & 7;
                    uint32_t sw = sw128((uint32_t)row * 128 + kg * 16);
                    cp_async16(sb + sw, Ah + (size_t)row * 1024 + k0 + kg * 8);
                }
                {
                    int row = g >> 4, kg = g & 15;
                    cp_async16(sb + OFF2_B + swB(row, kg * 16),
                               Bh + (size_t)(k0 + row) * 1024 + n0 + kg * 8);
                }
            }
            cp_commit();
            cp_wait<1>();
        } else {
            cp_wait<0>();
        }
        __syncthreads();

        const uint32_t base = sbase + buf * BUFSZ2;
        #pragma unroll
        for (int ks = 0; ks < 4; ks++) {
            const int kb = ks * 16;
            uint32_t ah[4][4], bh[4][2];
            #pragma unroll
            for (int mt = 0; mt < 4; mt++) {
                uint32_t sw = sw128((uint32_t)(arow + mt * 16) * 128 + (acol8 + kb) * 2);
                ldsm_x4(ah[mt], base + sw);
            }
            #pragma unroll
            for (int bt = 0; bt < 2; bt++) {
                uint32_t row = kb + t_krow;
                uint32_t nb  = (wn * 32 + bt * 16) * 2 + t_nb;
                uint32_t t[4];
                ldsm_x4_trans(t, base + OFF2_B + swB(row, nb));
                bh[bt * 2][0] = t[0]; bh[bt * 2][1] = t[1];
                bh[bt * 2 + 1][0] = t[2]; bh[bt * 2 + 1][1] = t[3];
            }
            #pragma unroll
            for (int mt = 0; mt < 4; mt++)
                #pragma unroll
                for (int nt = 0; nt < 4; nt++)
                    mma16816(c[mt][nt], ah[mt], bh[nt]);
        }
        __syncthreads();
        buf ^= 1;
    }

    // ---- epilogue: per-row sum of squares, deterministic reduction ----
    float* red = (float*)smem;                 // aliases staging (done with it)
    const int r0 = lane >> 2;
    #pragma unroll
    for (int mt = 0; mt < 4; mt++) {
        float s0 = 0.f, s1 = 0.f;
        #pragma unroll
        for (int nt = 0; nt < 4; nt++) {
            s0 = fmaf(c[mt][nt][0], c[mt][nt][0], fmaf(c[mt][nt][1], c[mt][nt][1], s0));
            s1 = fmaf(c[mt][nt][2], c[mt][nt][2], fmaf(c[mt][nt][3], c[mt][nt][3], s1));
        }
        s0 += __shfl_xor_sync(0xffffffffu, s0, 1);
        s0 += __shfl_xor_sync(0xffffffffu, s0, 2);
        s1 += __shfl_xor_sync(0xffffffffu, s1, 1);
        s1 += __shfl_xor_sync(0xffffffffu, s1, 2);
        if ((lane & 3) == 0) {
            red[wn * 128 + wm * 64 + mt * 16 + r0]     = s0;
            red[wn * 128 + wm * 64 + mt * 16 + r0 + 8] = s1;
        }
    }
    __syncthreads();
    if (tid < 128) {
        float v = red[tid] + red[128 + tid] + red[256 + tid] + red[384 + tid];
        g_A2P[((size_t)b * 8 + blockIdx.y) * Qn + q0 + tid] = v;
    }
}

// ---------------- K4: final logits ------------------------------------------
__global__ void final_kernel(float* __restrict__ out) {
    const int idx = blockIdx.x * blockDim.x + threadIdx.x;   // row = b*512 + q
    const int b = idx >> 9, q = idx & 511;
    float a2 = 0.f;
    #pragma unroll
    for (int nt = 0; nt < 8; nt++)
        a2 += g_A2P[((size_t)b * 8 + nt) * Qn + q];
    float dn = fmaxf(g_QN[q], 1e-12f) * fmaxf(sqrtf(a2), 1e-12f);
    out[(size_t)q * Bn + b] = g_DOT[idx] / dn;
}

// ---------------- launch ----------------------------------------------------
extern "C" void kernel_launch(void* const* d_in, const int* in_sizes, int n_in,
                              void* d_out, int out_size)
{
    const float* queries = (const float*)d_in[0];   // [512,1024]
    const float* tokens  = (const float*)d_in[1];   // [64,1024,1024]
    float* out = (float*)d_out;                     // [512,64]

    cudaFuncSetAttribute(gemm1_kernel,
                         cudaFuncAttributeMaxDynamicSharedMemorySize, GEMM1_SMEM);
    cudaFuncSetAttribute(gemm2_kernel,
                         cudaFuncAttributeMaxDynamicSharedMemorySize, GEMM2_SMEM);

    convert_q_kernel<<<512, 256>>>(queries);
    qnorm_kernel<<<64, 256>>>(queries);
    convert_tk_kernel<<<65536, 256>>>(tokens);
    gemm1_kernel<<<dim3(Qn / 128, Ln / 128, Bn), 256, GEMM1_SMEM>>>();
    softmax_kernel<<<Bn * Qn / 8, 256>>>();
    gemm2_kernel<<<dim3(Qn / 128, Dn / 128, Bn), 256, GEMM2_SMEM>>>();
    final_kernel<<<(Bn * Qn) / 256, 256>>>(out);
}

// round 8
// speedup vs baseline: 8.4904x; 1.2459x over previous
#include <cuda_runtime.h>
#include <cuda_fp16.h>
#include <cstdint>
#include <math.h>

// SimilarityLogit on GB300 via mma.sync (HMMA) fp16 GEMMs, fp32 accumulate.
//   queries      : [Q=512, D=1024]  fp32      (d_in[0])
//   local_tokens : [B=64, L=1024, D=1024] fp32 (d_in[1])
//   out          : [Q=512, B=64]   fp32  (out[q*64+b])
//
// Math: S = qT^t/32 ; P = softmax(S) ; agg = P T
//   out = dot(q,agg)/(max(||q||,eps) max(||agg||,eps))
// Identity: dot(q,agg) = 32 * sum_l P[l] S[l]  -> computed in softmax kernel.
// GEMM2 only supplies ||agg||^2 (error-tolerant). Tokens stored ONCE as fp16
// [l][d]; GEMM1 uses them K-major, GEMM2 loads its B fragments from the same
// layout via ldmatrix.trans. Q single fp16 (measured error transfer: one fp16
// operand ~3.5e-5 final rel_err; two independent ~5e-5, >> margin to 1e-3).

static constexpr int Qn = 512, Dn = 1024, Ln = 1024, Bn = 64;

// ---------------- scratch (device globals; no runtime allocation) ----------
__device__ __half g_Qh[(size_t)Qn * Dn];
__device__ __half g_TH[(size_t)Bn * Ln * Dn];          // tokens fp16 [b][l][d]
__device__ float  g_S[(size_t)Bn * Qn * Ln];
__device__ __half g_Ph[(size_t)Bn * Qn * Ln];
__device__ float  g_DOT[(size_t)Bn * Qn];
__device__ float  g_A2P[(size_t)Bn * 8 * Qn];          // per-(b, d-slab) row partials
__device__ float  g_QN[Qn];

// ---------------- PTX helpers ----------------------------------------------
__device__ __forceinline__ uint32_t smem_u32(const void* p) {
    uint32_t a;
    asm("{ .reg .u64 t; cvta.to.shared.u64 t, %1; cvt.u32.u64 %0, t; }"
        : "=r"(a) : "l"(p));
    return a;
}

__device__ __forceinline__ void cp_async16(uint32_t dst, const void* src) {
    asm volatile("cp.async.cg.shared.global [%0], [%1], 16;"
                 :: "r"(dst), "l"(src) : "memory");
}
__device__ __forceinline__ void cp_commit() {
    asm volatile("cp.async.commit_group;" ::: "memory");
}
template <int N>
__device__ __forceinline__ void cp_wait() {
    asm volatile("cp.async.wait_group %0;" :: "n"(N) : "memory");
}

__device__ __forceinline__ void ldsm_x4(uint32_t* r, uint32_t addr) {
    asm volatile("ldmatrix.sync.aligned.m8n8.x4.shared.b16 {%0,%1,%2,%3}, [%4];"
                 : "=r"(r[0]), "=r"(r[1]), "=r"(r[2]), "=r"(r[3]) : "r"(addr));
}

__device__ __forceinline__ void ldsm_x4_trans(uint32_t* r, uint32_t addr) {
    asm volatile("ldmatrix.sync.aligned.m8n8.x4.trans.shared.b16 {%0,%1,%2,%3}, [%4];"
                 : "=r"(r[0]), "=r"(r[1]), "=r"(r[2]), "=r"(r[3]) : "r"(addr));
}

__device__ __forceinline__ void mma16816(float* c, const uint32_t* a, const uint32_t* b) {
    asm volatile(
        "mma.sync.aligned.m16n8k16.row.col.f32.f16.f16.f32 "
        "{%0,%1,%2,%3}, {%4,%5,%6,%7}, {%8,%9}, {%0,%1,%2,%3};"
        : "+f"(c[0]), "+f"(c[1]), "+f"(c[2]), "+f"(c[3])
        : "r"(a[0]), "r"(a[1]), "r"(a[2]), "r"(a[3]), "r"(b[0]), "r"(b[1]));
}

__device__ __forceinline__ uint32_t sw128(uint32_t off) {
    return off ^ ((off >> 3) & 0x70);
}

// ---------------- K0a: convert queries (single fp16) ------------------------
__global__ void convert_q_kernel(const float* __restrict__ q) {
    int idx = blockIdx.x * blockDim.x + threadIdx.x;   // float4 index
    float4 v = ((const float4*)q)[idx];
    __half h0 = __float2half(v.x), h1 = __float2half(v.y);
    __half h2 = __float2half(v.z), h3 = __float2half(v.w);
    uint2 hp;
    hp.x = (uint32_t)__half_as_ushort(h0) | ((uint32_t)__half_as_ushort(h1) << 16);
    hp.y = (uint32_t)__half_as_ushort(h2) | ((uint32_t)__half_as_ushort(h3) << 16);
    ((uint2*)g_Qh)[idx] = hp;
}

// ---------------- K0b: query norms ------------------------------------------
__global__ void qnorm_kernel(const float* __restrict__ q) {
    const int warp = threadIdx.x >> 5, lane = threadIdx.x & 31;
    const int row = blockIdx.x * 8 + warp;
    const float4* qp = (const float4*)(q + (size_t)row * Dn);
    float s = 0.f;
    #pragma unroll
    for (int i = 0; i < 8; i++) {
        float4 v = qp[lane + i * 32];
        s = fmaf(v.x, v.x, fmaf(v.y, v.y, fmaf(v.z, v.z, fmaf(v.w, v.w, s))));
    }
    #pragma unroll
    for (int o = 16; o > 0; o >>= 1) s += __shfl_xor_sync(0xffffffffu, s, o);
    if (lane == 0) g_QN[row] = sqrtf(s);
}

// ---------------- K0c: convert tokens (single fp16) -------------------------
__global__ void convert_tk_kernel(const float* __restrict__ tok) {
    size_t idx = (size_t)blockIdx.x * blockDim.x + threadIdx.x;   // float4 index
    float4 v = ((const float4*)tok)[idx];
    uint2 hp;
    __half h0 = __float2half(v.x), h1 = __float2half(v.y);
    __half h2 = __float2half(v.z), h3 = __float2half(v.w);
    hp.x = (uint32_t)__half_as_ushort(h0) | ((uint32_t)__half_as_ushort(h1) << 16);
    hp.y = (uint32_t)__half_as_ushort(h2) | ((uint32_t)__half_as_ushort(h3) << 16);
    ((uint2*)g_TH)[idx] = hp;
}

// ---------------- K2: warp-per-row softmax + dot + fp16 P -------------------
__global__ void softmax_kernel() {
    const int warp = threadIdx.x >> 5, lane = threadIdx.x & 31;
    const int row = blockIdx.x * 8 + warp;             // = b*Qn + q
    const float4* srow = (const float4*)(g_S + (size_t)row * Ln);

    float4 v[8];
    #pragma unroll
    for (int i = 0; i < 8; i++) v[i] = srow[lane + i * 32];

    float m = -INFINITY;
    #pragma unroll
    for (int i = 0; i < 8; i++)
        m = fmaxf(m, fmaxf(fmaxf(v[i].x, v[i].y), fmaxf(v[i].z, v[i].w)));
    #pragma unroll
    for (int o = 16; o > 0; o >>= 1) m = fmaxf(m, __shfl_xor_sync(0xffffffffu, m, o));

    float s = 0.f, ev = 0.f;
    float4 e[8];
    #pragma unroll
    for (int i = 0; i < 8; i++) {
        e[i].x = expf(v[i].x - m); e[i].y = expf(v[i].y - m);
        e[i].z = expf(v[i].z - m); e[i].w = expf(v[i].w - m);
        s  += e[i].x + e[i].y + e[i].z + e[i].w;
        ev += e[i].x * v[i].x + e[i].y * v[i].y + e[i].z * v[i].z + e[i].w * v[i].w;
    }
    #pragma unroll
    for (int o = 16; o > 0; o >>= 1) {
        s  += __shfl_xor_sync(0xffffffffu, s, o);
        ev += __shfl_xor_sync(0xffffffffu, ev, o);
    }
    const float inv = 1.0f / s;
    if (lane == 0) g_DOT[row] = 32.0f * inv * ev;      // dot(q, agg), exact identity

    uint2* pout = (uint2*)(g_Ph + (size_t)row * Ln);
    #pragma unroll
    for (int i = 0; i < 8; i++) {
        __half h0 = __float2half(e[i].x * inv);
        __half h1 = __float2half(e[i].y * inv);
        __half h2 = __float2half(e[i].z * inv);
        __half h3 = __float2half(e[i].w * inv);
        uint2 hp;
        hp.x = (uint32_t)__half_as_ushort(h0) | ((uint32_t)__half_as_ushort(h1) << 16);
        hp.y = (uint32_t)__half_as_ushort(h2) | ((uint32_t)__half_as_ushort(h3) << 16);
        pout[lane + i * 32] = hp;
    }
}

// ---------------- K1: GEMM1 (single fp16: Qh.T) -----------------------------
// CTA tile 128x128, K chunks of 64. buf: Ah Bh (16K each) x2 = 64K.
static constexpr uint32_t OFF_BH = 16384;
static constexpr uint32_t BUFSZ  = 32768;
static constexpr int GEMM1_SMEM = 65536;

__global__ void __launch_bounds__(256, 1)
gemm1_kernel()
{
    extern __shared__ unsigned char smem[];
    const uint32_t sbase = smem_u32(smem);
    const int tid  = threadIdx.x;
    const int wid  = tid >> 5, lane = tid & 31;
    const int q0   = blockIdx.x * 128;
    const int n0   = blockIdx.y * 128;
    const int b    = blockIdx.z;

    const __half* Ah = g_Qh + (size_t)q0 * Dn;
    const __half* Bh = g_TH + (size_t)b * Ln * Dn + (size_t)n0 * Dn;
    float* Cg = g_S + ((size_t)b * Qn + q0) * Ln + n0;

    const int wm = wid >> 2, wn = wid & 3;
    const int arow  = wm * 64 + (lane & 7) + ((lane >> 3) & 1) * 8;
    const int acol8 = (lane >> 4) * 8;
    const int brow  = wn * 32 + (lane & 7) + (lane >> 4) * 8;
    const int bcol8 = ((lane >> 3) & 1) * 8;

    float c[4][4][4];
    #pragma unroll
    for (int mt = 0; mt < 4; mt++)
        #pragma unroll
        for (int nt = 0; nt < 4; nt++)
            #pragma unroll
            for (int i = 0; i < 4; i++) c[mt][nt][i] = 0.f;

    #pragma unroll
    for (int i = 0; i < 4; i++) {
        int g = tid + i * 256;
        int row = g >> 3, kg = g & 7;
        uint32_t sw = sw128((uint32_t)row * 128 + kg * 16);
        size_t src = (size_t)row * 1024 + kg * 8;
        cp_async16(sbase + sw,          Ah + src);
        cp_async16(sbase + OFF_BH + sw, Bh + src);
    }
    cp_commit();

    int buf = 0;
    for (int kc = 0; kc < 16; kc++) {
        if (kc + 1 < 16) {
            uint32_t sb = sbase + (buf ^ 1) * BUFSZ;
            int k0 = (kc + 1) * 64;
            #pragma unroll
            for (int i = 0; i < 4; i++) {
                int g = tid + i * 256;
                int row = g >> 3, kg = g & 7;
                uint32_t sw = sw128((uint32_t)row * 128 + kg * 16);
                size_t src = (size_t)row * 1024 + k0 + kg * 8;
                cp_async16(sb + sw,          Ah + src);
                cp_async16(sb + OFF_BH + sw, Bh + src);
            }
            cp_commit();
            cp_wait<1>();
        } else {
            cp_wait<0>();
        }
        __syncthreads();

        const uint32_t base = sbase + buf * BUFSZ;
        #pragma unroll
        for (int ks = 0; ks < 4; ks++) {
            const int kb = ks * 16;
            uint32_t ah[4][4], bh[4][2];
            #pragma unroll
            for (int mt = 0; mt < 4; mt++) {
                uint32_t sw = sw128((uint32_t)(arow + mt * 16) * 128 + (acol8 + kb) * 2);
                ldsm_x4(ah[mt], base + sw);
            }
            #pragma unroll
            for (int bt = 0; bt < 2; bt++) {
                uint32_t sw = sw128((uint32_t)(brow + bt * 16) * 128 + (bcol8 + kb) * 2);
                uint32_t t[4];
                ldsm_x4(t, base + OFF_BH + sw);
                bh[bt * 2][0] = t[0]; bh[bt * 2][1] = t[1];
                bh[bt * 2 + 1][0] = t[2]; bh[bt * 2 + 1][1] = t[3];
            }
            #pragma unroll
            for (int mt = 0; mt < 4; mt++)
                #pragma unroll
                for (int nt = 0; nt < 4; nt++)
                    mma16816(c[mt][nt], ah[mt], bh[nt]);
        }
        __syncthreads();
        buf ^= 1;
    }

    const int r0 = lane >> 2, c0 = (lane & 3) * 2;
    #pragma unroll
    for (int mt = 0; mt < 4; mt++)
        #pragma unroll
        for (int nt = 0; nt < 4; nt++) {
            int row = wm * 64 + mt * 16 + r0;
            int col = wn * 32 + nt * 8 + c0;
            float2 v0 = make_float2(c[mt][nt][0] * 0.03125f, c[mt][nt][1] * 0.03125f);
            float2 v1 = make_float2(c[mt][nt][2] * 0.03125f, c[mt][nt][3] * 0.03125f);
            *(float2*)(Cg + (size_t)row * 1024 + col) = v0;
            *(float2*)(Cg + (size_t)(row + 8) * 1024 + col) = v1;
        }
}

// ---------------- K3: GEMM2 (fp16, B via ldmatrix.trans) --------------------
// A tile: Ph 128(q) x 64(l), K-major, 16K. B tile: TH 64(l) x 128(d), 16K.
// B smem layout: row = l (64 rows x 256B), 16B granule g in row: swizzled
//   (g&7) ^ (row&7) within each 128B half -> conflict-free trans-ldmatrix.
static constexpr uint32_t OFF2_B = 16384;
static constexpr uint32_t BUFSZ2 = 32768;
static constexpr int GEMM2_SMEM = 65536;

__device__ __forceinline__ uint32_t swB(uint32_t row, uint32_t nbyte) {
    uint32_t g = nbyte >> 4;
    uint32_t g7 = (g & 7) ^ (row & 7);
    return row * 256 + (g & 8) * 16 + g7 * 16;
}

__global__ void __launch_bounds__(256, 1)
gemm2_kernel()
{
    extern __shared__ unsigned char smem[];
    const uint32_t sbase = smem_u32(smem);
    const int tid  = threadIdx.x;
    const int wid  = tid >> 5, lane = tid & 31;
    const int q0   = blockIdx.x * 128;
    const int n0   = blockIdx.y * 128;     // d-slab
    const int b    = blockIdx.z;

    const __half* Ah = g_Ph + ((size_t)b * Qn + q0) * Ln;
    const __half* Bh = g_TH + (size_t)b * Ln * Dn;   // [l][d]

    const int wm = wid >> 2, wn = wid & 3;
    const int arow  = wm * 64 + (lane & 7) + ((lane >> 3) & 1) * 8;
    const int acol8 = (lane >> 4) * 8;

    const int t_r    = lane & 7;
    const int t_krow = ((lane >> 3) & 1) * 8 + t_r;
    const int t_nb   = (lane >> 4) * 16;

    float c[4][4][4];
    #pragma unroll
    for (int mt = 0; mt < 4; mt++)
        #pragma unroll
        for (int nt = 0; nt < 4; nt++)
            #pragma unroll
            for (int i = 0; i < 4; i++) c[mt][nt][i] = 0.f;

    #pragma unroll
    for (int i = 0; i < 4; i++) {
        int g = tid + i * 256;
        {   // A: 128 rows x 8 granules
            int row = g >> 3, kg = g & 7;
            uint32_t sw = sw128((uint32_t)row * 128 + kg * 16);
            cp_async16(sbase + sw, Ah + (size_t)row * 1024 + kg * 8);
        }
        {   // B: 64 rows x 16 granules
            int row = g >> 4, kg = g & 15;
            cp_async16(sbase + OFF2_B + swB(row, kg * 16),
                       Bh + (size_t)row * 1024 + n0 + kg * 8);
        }
    }
    cp_commit();

    int buf = 0;
    for (int kc = 0; kc < 16; kc++) {
        if (kc + 1 < 16) {
            uint32_t sb = sbase + (buf ^ 1) * BUFSZ2;
            int k0 = (kc + 1) * 64;
            #pragma unroll
            for (int i = 0; i < 4; i++) {
                int g = tid + i * 256;
                {
                    int row = g >> 3, kg = g & 7;
                    uint32_t sw = sw128((uint32_t)row * 128 + kg * 16);
                    cp_async16(sb + sw, Ah + (size_t)row * 1024 + k0 + kg * 8);
                }
                {
                    int row = g >> 4, kg = g & 15;
                    cp_async16(sb + OFF2_B + swB(row, kg * 16),
                               Bh + (size_t)(k0 + row) * 1024 + n0 + kg * 8);
                }
            }
            cp_commit();
            cp_wait<1>();
        } else {
            cp_wait<0>();
        }
        __syncthreads();

        const uint32_t base = sbase + buf * BUFSZ2;
        #pragma unroll
        for (int ks = 0; ks < 4; ks++) {
            const int kb = ks * 16;
            uint32_t ah[4][4], bh[4][2];
            #pragma unroll
            for (int mt = 0; mt < 4; mt++) {
                uint32_t sw = sw128((uint32_t)(arow + mt * 16) * 128 + (acol8 + kb) * 2);
                ldsm_x4(ah[mt], base + sw);
            }
            #pragma unroll
            for (int bt = 0; bt < 2; bt++) {
                uint32_t row = kb + t_krow;
                uint32_t nb  = (wn * 32 + bt * 16) * 2 + t_nb;
                uint32_t t[4];
                ldsm_x4_trans(t, base + OFF2_B + swB(row, nb));
                bh[bt * 2][0] = t[0]; bh[bt * 2][1] = t[1];
                bh[bt * 2 + 1][0] = t[2]; bh[bt * 2 + 1][1] = t[3];
            }
            #pragma unroll
            for (int mt = 0; mt < 4; mt++)
                #pragma unroll
                for (int nt = 0; nt < 4; nt++)
                    mma16816(c[mt][nt], ah[mt], bh[nt]);
        }
        __syncthreads();
        buf ^= 1;
    }

    // ---- epilogue: per-row sum of squares, deterministic reduction ----
    float* red = (float*)smem;                 // aliases staging (done with it)
    const int r0 = lane >> 2;
    #pragma unroll
    for (int mt = 0; mt < 4; mt++) {
        float s0 = 0.f, s1 = 0.f;
        #pragma unroll
        for (int nt = 0; nt < 4; nt++) {
            s0 = fmaf(c[mt][nt][0], c[mt][nt][0], fmaf(c[mt][nt][1], c[mt][nt][1], s0));
            s1 = fmaf(c[mt][nt][2], c[mt][nt][2], fmaf(c[mt][nt][3], c[mt][nt][3], s1));
        }
        s0 += __shfl_xor_sync(0xffffffffu, s0, 1);
        s0 += __shfl_xor_sync(0xffffffffu, s0, 2);
        s1 += __shfl_xor_sync(0xffffffffu, s1, 1);
        s1 += __shfl_xor_sync(0xffffffffu, s1, 2);
        if ((lane & 3) == 0) {
            red[wn * 128 + wm * 64 + mt * 16 + r0]     = s0;
            red[wn * 128 + wm * 64 + mt * 16 + r0 + 8] = s1;
        }
    }
    __syncthreads();
    if (tid < 128) {
        float v = red[tid] + red[128 + tid] + red[256 + tid] + red[384 + tid];
        g_A2P[((size_t)b * 8 + blockIdx.y) * Qn + q0 + tid] = v;
    }
}

// ---------------- K4: final logits ------------------------------------------
__global__ void final_kernel(float* __restrict__ out) {
    const int idx = blockIdx.x * blockDim.x + threadIdx.x;   // row = b*512 + q
    const int b = idx >> 9, q = idx & 511;
    float a2 = 0.f;
    #pragma unroll
    for (int nt = 0; nt < 8; nt++)
        a2 += g_A2P[((size_t)b * 8 + nt) * Qn + q];
    float dn = fmaxf(g_QN[q], 1e-12f) * fmaxf(sqrtf(a2), 1e-12f);
    out[(size_t)q * Bn + b] = g_DOT[idx] / dn;
}

// ---------------- launch ----------------------------------------------------
extern "C" void kernel_launch(void* const* d_in, const int* in_sizes, int n_in,
                              void* d_out, int out_size)
{
    const float* queries = (const float*)d_in[0];   // [512,1024]
    const float* tokens  = (const float*)d_in[1];   // [64,1024,1024]
    float* out = (float*)d_out;                     // [512,64]

    cudaFuncSetAttribute(gemm1_kernel,
                         cudaFuncAttributeMaxDynamicSharedMemorySize, GEMM1_SMEM);
    cudaFuncSetAttribute(gemm2_kernel,
                         cudaFuncAttributeMaxDynamicSharedMemorySize, GEMM2_SMEM);

    convert_q_kernel<<<512, 256>>>(queries);
    qnorm_kernel<<<64, 256>>>(queries);
    convert_tk_kernel<<<65536, 256>>>(tokens);
    gemm1_kernel<<<dim3(Qn / 128, Ln / 128, Bn), 256, GEMM1_SMEM>>>();
    softmax_kernel<<<Bn * Qn / 8, 256>>>();
    gemm2_kernel<<<dim3(Qn / 128, Dn / 128, Bn), 256, GEMM2_SMEM>>>();
    final_kernel<<<(Bn * Qn) / 256, 256>>>(out);
}

// round 9
// speedup vs baseline: 8.6313x; 1.0166x over previous
#include <cuda_runtime.h>
#include <cuda_fp16.h>
#include <cstdint>
#include <math.h>

// SimilarityLogit on GB300 via mma.sync (HMMA) fp16 GEMMs, fp32 accumulate.
//   queries      : [Q=512, D=1024]  fp32      (d_in[0])
//   local_tokens : [B=64, L=1024, D=1024] fp32 (d_in[1])
//   out          : [Q=512, B=64]   fp32  (out[q*64+b])
//
// Math: S = qT^t/32 ; P = softmax(S) ; agg = P T
//   out = dot(q,agg)/(max(||q||,eps) max(||agg||,eps))
// Identity: dot(q,agg) = 32 * sum_l P[l] S[l]  -> computed in softmax kernel.
// GEMM2 only supplies ||agg||^2 (error-tolerant). Tokens stored ONCE as fp16
// [l][d]; GEMM1 uses them K-major, GEMM2 loads its B fragments via
// ldmatrix.trans. Q single fp16. Both GEMMs: 4-stage cp.async pipeline
// (3 chunks in flight) to cover memory latency at 1 CTA/SM.

static constexpr int Qn = 512, Dn = 1024, Ln = 1024, Bn = 64;

// ---------------- scratch (device globals; no runtime allocation) ----------
__device__ __half g_Qh[(size_t)Qn * Dn];
__device__ __half g_TH[(size_t)Bn * Ln * Dn];          // tokens fp16 [b][l][d]
__device__ float  g_S[(size_t)Bn * Qn * Ln];
__device__ __half g_Ph[(size_t)Bn * Qn * Ln];
__device__ float  g_DOT[(size_t)Bn * Qn];
__device__ float  g_A2P[(size_t)Bn * 8 * Qn];          // per-(b, d-slab) row partials
__device__ float  g_QN[Qn];

// ---------------- PTX helpers ----------------------------------------------
__device__ __forceinline__ uint32_t smem_u32(const void* p) {
    uint32_t a;
    asm("{ .reg .u64 t; cvta.to.shared.u64 t, %1; cvt.u32.u64 %0, t; }"
        : "=r"(a) : "l"(p));
    return a;
}

__device__ __forceinline__ void cp_async16(uint32_t dst, const void* src) {
    asm volatile("cp.async.cg.shared.global [%0], [%1], 16;"
                 :: "r"(dst), "l"(src) : "memory");
}
__device__ __forceinline__ void cp_commit() {
    asm volatile("cp.async.commit_group;" ::: "memory");
}
template <int N>
__device__ __forceinline__ void cp_wait() {
    asm volatile("cp.async.wait_group %0;" :: "n"(N) : "memory");
}

__device__ __forceinline__ void ldsm_x4(uint32_t* r, uint32_t addr) {
    asm volatile("ldmatrix.sync.aligned.m8n8.x4.shared.b16 {%0,%1,%2,%3}, [%4];"
                 : "=r"(r[0]), "=r"(r[1]), "=r"(r[2]), "=r"(r[3]) : "r"(addr));
}

__device__ __forceinline__ void ldsm_x4_trans(uint32_t* r, uint32_t addr) {
    asm volatile("ldmatrix.sync.aligned.m8n8.x4.trans.shared.b16 {%0,%1,%2,%3}, [%4];"
                 : "=r"(r[0]), "=r"(r[1]), "=r"(r[2]), "=r"(r[3]) : "r"(addr));
}

__device__ __forceinline__ void mma16816(float* c, const uint32_t* a, const uint32_t* b) {
    asm volatile(
        "mma.sync.aligned.m16n8k16.row.col.f32.f16.f16.f32 "
        "{%0,%1,%2,%3}, {%4,%5,%6,%7}, {%8,%9}, {%0,%1,%2,%3};"
        : "+f"(c[0]), "+f"(c[1]), "+f"(c[2]), "+f"(c[3])
        : "r"(a[0]), "r"(a[1]), "r"(a[2]), "r"(a[3]), "r"(b[0]), "r"(b[1]));
}

__device__ __forceinline__ uint32_t sw128(uint32_t off) {
    return off ^ ((off >> 3) & 0x70);
}

// ---------------- K0a: convert queries (single fp16) ------------------------
__global__ void convert_q_kernel(const float* __restrict__ q) {
    int idx = blockIdx.x * blockDim.x + threadIdx.x;   // float4 index
    float4 v = ((const float4*)q)[idx];
    __half h0 = __float2half(v.x), h1 = __float2half(v.y);
    __half h2 = __float2half(v.z), h3 = __float2half(v.w);
    uint2 hp;
    hp.x = (uint32_t)__half_as_ushort(h0) | ((uint32_t)__half_as_ushort(h1) << 16);
    hp.y = (uint32_t)__half_as_ushort(h2) | ((uint32_t)__half_as_ushort(h3) << 16);
    ((uint2*)g_Qh)[idx] = hp;
}

// ---------------- K0b: query norms ------------------------------------------
__global__ void qnorm_kernel(const float* __restrict__ q) {
    const int warp = threadIdx.x >> 5, lane = threadIdx.x & 31;
    const int row = blockIdx.x * 8 + warp;
    const float4* qp = (const float4*)(q + (size_t)row * Dn);
    float s = 0.f;
    #pragma unroll
    for (int i = 0; i < 8; i++) {
        float4 v = qp[lane + i * 32];
        s = fmaf(v.x, v.x, fmaf(v.y, v.y, fmaf(v.z, v.z, fmaf(v.w, v.w, s))));
    }
    #pragma unroll
    for (int o = 16; o > 0; o >>= 1) s += __shfl_xor_sync(0xffffffffu, s, o);
    if (lane == 0) g_QN[row] = sqrtf(s);
}

// ---------------- K0c: convert tokens (single fp16) -------------------------
__global__ void convert_tk_kernel(const float* __restrict__ tok) {
    size_t idx = (size_t)blockIdx.x * blockDim.x + threadIdx.x;   // float4 index
    float4 v = ((const float4*)tok)[idx];
    uint2 hp;
    __half h0 = __float2half(v.x), h1 = __float2half(v.y);
    __half h2 = __float2half(v.z), h3 = __float2half(v.w);
    hp.x = (uint32_t)__half_as_ushort(h0) | ((uint32_t)__half_as_ushort(h1) << 16);
    hp.y = (uint32_t)__half_as_ushort(h2) | ((uint32_t)__half_as_ushort(h3) << 16);
    ((uint2*)g_TH)[idx] = hp;
}

// ---------------- K2: warp-per-row softmax + dot + fp16 P -------------------
__global__ void softmax_kernel() {
    const int warp = threadIdx.x >> 5, lane = threadIdx.x & 31;
    const int row = blockIdx.x * 8 + warp;             // = b*Qn + q
    const float4* srow = (const float4*)(g_S + (size_t)row * Ln);

    float4 v[8];
    #pragma unroll
    for (int i = 0; i < 8; i++) v[i] = srow[lane + i * 32];

    float m = -INFINITY;
    #pragma unroll
    for (int i = 0; i < 8; i++)
        m = fmaxf(m, fmaxf(fmaxf(v[i].x, v[i].y), fmaxf(v[i].z, v[i].w)));
    #pragma unroll
    for (int o = 16; o > 0; o >>= 1) m = fmaxf(m, __shfl_xor_sync(0xffffffffu, m, o));

    float s = 0.f, ev = 0.f;
    float4 e[8];
    #pragma unroll
    for (int i = 0; i < 8; i++) {
        e[i].x = expf(v[i].x - m); e[i].y = expf(v[i].y - m);
        e[i].z = expf(v[i].z - m); e[i].w = expf(v[i].w - m);
        s  += e[i].x + e[i].y + e[i].z + e[i].w;
        ev += e[i].x * v[i].x + e[i].y * v[i].y + e[i].z * v[i].z + e[i].w * v[i].w;
    }
    #pragma unroll
    for (int o = 16; o > 0; o >>= 1) {
        s  += __shfl_xor_sync(0xffffffffu, s, o);
        ev += __shfl_xor_sync(0xffffffffu, ev, o);
    }
    const float inv = 1.0f / s;
    if (lane == 0) g_DOT[row] = 32.0f * inv * ev;      // dot(q, agg), exact identity

    uint2* pout = (uint2*)(g_Ph + (size_t)row * Ln);
    #pragma unroll
    for (int i = 0; i < 8; i++) {
        __half h0 = __float2half(e[i].x * inv);
        __half h1 = __float2half(e[i].y * inv);
        __half h2 = __float2half(e[i].z * inv);
        __half h3 = __float2half(e[i].w * inv);
        uint2 hp;
        hp.x = (uint32_t)__half_as_ushort(h0) | ((uint32_t)__half_as_ushort(h1) << 16);
        hp.y = (uint32_t)__half_as_ushort(h2) | ((uint32_t)__half_as_ushort(h3) << 16);
        pout[lane + i * 32] = hp;
    }
}

// ---------------- K1: GEMM1 (single fp16: Qh.T), 4-stage pipeline -----------
// CTA tile 128x128, K chunks of 64. stage buf: Ah Bh (16K each) = 32K; x4.
static constexpr uint32_t OFF_BH = 16384;
static constexpr uint32_t BUFSZ  = 32768;
static constexpr int GEMM1_SMEM = 131072;
static constexpr int NSTAGE = 4;

__global__ void __launch_bounds__(256, 1)
gemm1_kernel()
{
    extern __shared__ unsigned char smem[];
    const uint32_t sbase = smem_u32(smem);
    const int tid  = threadIdx.x;
    const int wid  = tid >> 5, lane = tid & 31;
    const int q0   = blockIdx.x * 128;
    const int n0   = blockIdx.y * 128;
    const int b    = blockIdx.z;

    const __half* Ah = g_Qh + (size_t)q0 * Dn;
    const __half* Bh = g_TH + (size_t)b * Ln * Dn + (size_t)n0 * Dn;
    float* Cg = g_S + ((size_t)b * Qn + q0) * Ln + n0;

    const int wm = wid >> 2, wn = wid & 3;
    const int arow  = wm * 64 + (lane & 7) + ((lane >> 3) & 1) * 8;
    const int acol8 = (lane >> 4) * 8;
    const int brow  = wn * 32 + (lane & 7) + (lane >> 4) * 8;
    const int bcol8 = ((lane >> 3) & 1) * 8;

    float c[4][4][4];
    #pragma unroll
    for (int mt = 0; mt < 4; mt++)
        #pragma unroll
        for (int nt = 0; nt < 4; nt++)
            #pragma unroll
            for (int i = 0; i < 4; i++) c[mt][nt][i] = 0.f;

    // prologue: stage chunks 0..2
    #pragma unroll
    for (int s = 0; s < NSTAGE - 1; s++) {
        uint32_t sb = sbase + s * BUFSZ;
        int k0 = s * 64;
        #pragma unroll
        for (int i = 0; i < 4; i++) {
            int g = tid + i * 256;
            int row = g >> 3, kg = g & 7;
            uint32_t sw = sw128((uint32_t)row * 128 + kg * 16);
            size_t src = (size_t)row * 1024 + k0 + kg * 8;
            cp_async16(sb + sw,          Ah + src);
            cp_async16(sb + OFF_BH + sw, Bh + src);
        }
        cp_commit();
    }

    for (int kc = 0; kc < 16; kc++) {
        cp_wait<NSTAGE - 2>();      // oldest committed chunk (kc) has landed
        __syncthreads();            // visibility + WAR for buffer (kc+3)%4

        if (kc + NSTAGE - 1 < 16) {
            uint32_t sb = sbase + ((kc + NSTAGE - 1) & 3) * BUFSZ;
            int k0 = (kc + NSTAGE - 1) * 64;
            #pragma unroll
            for (int i = 0; i < 4; i++) {
                int g = tid + i * 256;
                int row = g >> 3, kg = g & 7;
                uint32_t sw = sw128((uint32_t)row * 128 + kg * 16);
                size_t src = (size_t)row * 1024 + k0 + kg * 8;
                cp_async16(sb + sw,          Ah + src);
                cp_async16(sb + OFF_BH + sw, Bh + src);
            }
            cp_commit();
        } else {
            cp_commit();            // keep group count in lockstep with waits
        }

        const uint32_t base = sbase + (kc & 3) * BUFSZ;
        #pragma unroll
        for (int ks = 0; ks < 4; ks++) {
            const int kb = ks * 16;
            uint32_t ah[4][4], bh[4][2];
            #pragma unroll
            for (int mt = 0; mt < 4; mt++) {
                uint32_t sw = sw128((uint32_t)(arow + mt * 16) * 128 + (acol8 + kb) * 2);
                ldsm_x4(ah[mt], base + sw);
            }
            #pragma unroll
            for (int bt = 0; bt < 2; bt++) {
                uint32_t sw = sw128((uint32_t)(brow + bt * 16) * 128 + (bcol8 + kb) * 2);
                uint32_t t[4];
                ldsm_x4(t, base + OFF_BH + sw);
                bh[bt * 2][0] = t[0]; bh[bt * 2][1] = t[1];
                bh[bt * 2 + 1][0] = t[2]; bh[bt * 2 + 1][1] = t[3];
            }
            #pragma unroll
            for (int mt = 0; mt < 4; mt++)
                #pragma unroll
                for (int nt = 0; nt < 4; nt++)
                    mma16816(c[mt][nt], ah[mt], bh[nt]);
        }
    }

    const int r0 = lane >> 2, c0 = (lane & 3) * 2;
    #pragma unroll
    for (int mt = 0; mt < 4; mt++)
        #pragma unroll
        for (int nt = 0; nt < 4; nt++) {
            int row = wm * 64 + mt * 16 + r0;
            int col = wn * 32 + nt * 8 + c0;
            float2 v0 = make_float2(c[mt][nt][0] * 0.03125f, c[mt][nt][1] * 0.03125f);
            float2 v1 = make_float2(c[mt][nt][2] * 0.03125f, c[mt][nt][3] * 0.03125f);
            *(float2*)(Cg + (size_t)row * 1024 + col) = v0;
            *(float2*)(Cg + (size_t)(row + 8) * 1024 + col) = v1;
        }
}

// ---------------- K3: GEMM2 (fp16, B via ldmatrix.trans), 4-stage -----------
// A tile: Ph 128(q) x 64(l), K-major, 16K. B tile: TH 64(l) x 128(d), 16K.
// B smem layout: row = l (64 rows x 256B), granule swizzle (g&7)^(row&7).
static constexpr uint32_t OFF2_B = 16384;
static constexpr uint32_t BUFSZ2 = 32768;
static constexpr int GEMM2_SMEM = 131072;

__device__ __forceinline__ uint32_t swB(uint32_t row, uint32_t nbyte) {
    uint32_t g = nbyte >> 4;
    uint32_t g7 = (g & 7) ^ (row & 7);
    return row * 256 + (g & 8) * 16 + g7 * 16;
}

__global__ void __launch_bounds__(256, 1)
gemm2_kernel()
{
    extern __shared__ unsigned char smem[];
    const uint32_t sbase = smem_u32(smem);
    const int tid  = threadIdx.x;
    const int wid  = tid >> 5, lane = tid & 31;
    const int q0   = blockIdx.x * 128;
    const int n0   = blockIdx.y * 128;     // d-slab
    const int b    = blockIdx.z;

    const __half* Ah = g_Ph + ((size_t)b * Qn + q0) * Ln;
    const __half* Bh = g_TH + (size_t)b * Ln * Dn;   // [l][d]

    const int wm = wid >> 2, wn = wid & 3;
    const int arow  = wm * 64 + (lane & 7) + ((lane >> 3) & 1) * 8;
    const int acol8 = (lane >> 4) * 8;

    const int t_r    = lane & 7;
    const int t_krow = ((lane >> 3) & 1) * 8 + t_r;
    const int t_nb   = (lane >> 4) * 16;

    float c[4][4][4];
    #pragma unroll
    for (int mt = 0; mt < 4; mt++)
        #pragma unroll
        for (int nt = 0; nt < 4; nt++)
            #pragma unroll
            for (int i = 0; i < 4; i++) c[mt][nt][i] = 0.f;

    // prologue: stage chunks 0..2
    #pragma unroll
    for (int s = 0; s < NSTAGE - 1; s++) {
        uint32_t sb = sbase + s * BUFSZ2;
        int k0 = s * 64;
        #pragma unroll
        for (int i = 0; i < 4; i++) {
            int g = tid + i * 256;
            {   // A: 128 rows x 8 granules
                int row = g >> 3, kg = g & 7;
                uint32_t sw = sw128((uint32_t)row * 128 + kg * 16);
                cp_async16(sb + sw, Ah + (size_t)row * 1024 + k0 + kg * 8);
            }
            {   // B: 64 rows x 16 granules
                int row = g >> 4, kg = g & 15;
                cp_async16(sb + OFF2_B + swB(row, kg * 16),
                           Bh + (size_t)(k0 + row) * 1024 + n0 + kg * 8);
            }
        }
        cp_commit();
    }

    for (int kc = 0; kc < 16; kc++) {
        cp_wait<NSTAGE - 2>();
        __syncthreads();

        if (kc + NSTAGE - 1 < 16) {
            uint32_t sb = sbase + ((kc + NSTAGE - 1) & 3) * BUFSZ2;
            int k0 = (kc + NSTAGE - 1) * 64;
            #pragma unroll
            for (int i = 0; i < 4; i++) {
                int g = tid + i * 256;
                {
                    int row = g >> 3, kg = g & 7;
                    uint32_t sw = sw128((uint32_t)row * 128 + kg * 16);
                    cp_async16(sb + sw, Ah + (size_t)row * 1024 + k0 + kg * 8);
                }
                {
                    int row = g >> 4, kg = g & 15;
                    cp_async16(sb + OFF2_B + swB(row, kg * 16),
                               Bh + (size_t)(k0 + row) * 1024 + n0 + kg * 8);
                }
            }
            cp_commit();
        } else {
            cp_commit();
        }

        const uint32_t base = sbase + (kc & 3) * BUFSZ2;
        #pragma unroll
        for (int ks = 0; ks < 4; ks++) {
            const int kb = ks * 16;
            uint32_t ah[4][4], bh[4][2];
            #pragma unroll
            for (int mt = 0; mt < 4; mt++) {
                uint32_t sw = sw128((uint32_t)(arow + mt * 16) * 128 + (acol8 + kb) * 2);
                ldsm_x4(ah[mt], base + sw);
            }
            #pragma unroll
            for (int bt = 0; bt < 2; bt++) {
                uint32_t row = kb + t_krow;
                uint32_t nb  = (wn * 32 + bt * 16) * 2 + t_nb;
                uint32_t t[4];
                ldsm_x4_trans(t, base + OFF2_B + swB(row, nb));
                bh[bt * 2][0] = t[0]; bh[bt * 2][1] = t[1];
                bh[bt * 2 + 1][0] = t[2]; bh[bt * 2 + 1][1] = t[3];
            }
            #pragma unroll
            for (int mt = 0; mt < 4; mt++)
                #pragma unroll
                for (int nt = 0; nt < 4; nt++)
                    mma16816(c[mt][nt], ah[mt], bh[nt]);
        }
    }

    __syncthreads();   // all warps done reading staging before smem reuse

    // ---- epilogue: per-row sum of squares, deterministic reduction ----
    float* red = (float*)smem;                 // aliases staging (done with it)
    const int r0 = lane >> 2;
    #pragma unroll
    for (int mt = 0; mt < 4; mt++) {
        float s0 = 0.f, s1 = 0.f;
        #pragma unroll
        for (int nt = 0; nt < 4; nt++) {
            s0 = fmaf(c[mt][nt][0], c[mt][nt][0], fmaf(c[mt][nt][1], c[mt][nt][1], s0));
            s1 = fmaf(c[mt][nt][2], c[mt][nt][2], fmaf(c[mt][nt][3], c[mt][nt][3], s1));
        }
        s0 += __shfl_xor_sync(0xffffffffu, s0, 1);
        s0 += __shfl_xor_sync(0xffffffffu, s0, 2);
        s1 += __shfl_xor_sync(0xffffffffu, s1, 1);
        s1 += __shfl_xor_sync(0xffffffffu, s1, 2);
        if ((lane & 3) == 0) {
            red[wn * 128 + wm * 64 + mt * 16 + r0]     = s0;
            red[wn * 128 + wm * 64 + mt * 16 + r0 + 8] = s1;
        }
    }
    __syncthreads();
    if (tid < 128) {
        float v = red[tid] + red[128 + tid] + red[256 + tid] + red[384 + tid];
        g_A2P[((size_t)b * 8 + blockIdx.y) * Qn + q0 + tid] = v;
    }
}

// ---------------- K4: final logits ------------------------------------------
__global__ void final_kernel(float* __restrict__ out) {
    const int idx = blockIdx.x * blockDim.x + threadIdx.x;   // row = b*512 + q
    const int b = idx >> 9, q = idx & 511;
    float a2 = 0.f;
    #pragma unroll
    for (int nt = 0; nt < 8; nt++)
        a2 += g_A2P[((size_t)b * 8 + nt) * Qn + q];
    float dn = fmaxf(g_QN[q], 1e-12f) * fmaxf(sqrtf(a2), 1e-12f);
    out[(size_t)q * Bn + b] = g_DOT[idx] / dn;
}

// ---------------- launch ----------------------------------------------------
extern "C" void kernel_launch(void* const* d_in, const int* in_sizes, int n_in,
                              void* d_out, int out_size)
{
    const float* queries = (const float*)d_in[0];   // [512,1024]
    const float* tokens  = (const float*)d_in[1];   // [64,1024,1024]
    float* out = (float*)d_out;                     // [512,64]

    cudaFuncSetAttribute(gemm1_kernel,
                         cudaFuncAttributeMaxDynamicSharedMemorySize, GEMM1_SMEM);
    cudaFuncSetAttribute(gemm2_kernel,
                         cudaFuncAttributeMaxDynamicSharedMemorySize, GEMM2_SMEM);

    convert_q_kernel<<<512, 256>>>(queries);
    qnorm_kernel<<<64, 256>>>(queries);
    convert_tk_kernel<<<65536, 256>>>(tokens);
    gemm1_kernel<<<dim3(Qn / 128, Ln / 128, Bn), 256, GEMM1_SMEM>>>();
    softmax_kernel<<<Bn * Qn / 8, 256>>>();
    gemm2_kernel<<<dim3(Qn / 128, Dn / 128, Bn), 256, GEMM2_SMEM>>>();
    final_kernel<<<(Bn * Qn) / 256, 256>>>(out);
}

// round 10
// speedup vs baseline: 9.7081x; 1.1247x over previous
#include <cuda_runtime.h>
#include <cuda_fp16.h>
#include <cstdint>
#include <math.h>

// SimilarityLogit on GB300 via mma.sync (HMMA) fp16 GEMMs, fp32 accumulate.
//   queries      : [Q=512, D=1024]  fp32      (d_in[0])
//   local_tokens : [B=64, L=1024, D=1024] fp32 (d_in[1])
//   out          : [Q=512, B=64]   fp32  (out[q*64+b])
//
// Math: S = qT^t/32 ; P = softmax(S) ; agg = P T
//   out = dot(q,agg)/(max(||q||,eps) max(||agg||,eps))
// Identity: dot(q,agg) = 32 * sum_l P[l] S[l]  -> computed in softmax kernel.
// GEMM2 only supplies ||agg||^2. Tokens stored ONCE fp16 [l][d]; GEMM1 uses
// them K-major, GEMM2 via ldmatrix.trans. Q single fp16.
// This round: CTA tile 128x256, warp tile 64x64 -> MMA:LDSM ratio 4.0
// (was 2.67) to cover ldsm latency at 2 warps/SMSP.

static constexpr int Qn = 512, Dn = 1024, Ln = 1024, Bn = 64;

// ---------------- scratch (device globals; no runtime allocation) ----------
__device__ __half g_Qh[(size_t)Qn * Dn];
__device__ __half g_TH[(size_t)Bn * Ln * Dn];          // tokens fp16 [b][l][d]
__device__ float  g_S[(size_t)Bn * Qn * Ln];
__device__ __half g_Ph[(size_t)Bn * Qn * Ln];
__device__ float  g_DOT[(size_t)Bn * Qn];
__device__ float  g_A2P[(size_t)Bn * 4 * Qn];          // per-(b, d-slab) row partials
__device__ float  g_QN[Qn];

// ---------------- PTX helpers ----------------------------------------------
__device__ __forceinline__ uint32_t smem_u32(const void* p) {
    uint32_t a;
    asm("{ .reg .u64 t; cvta.to.shared.u64 t, %1; cvt.u32.u64 %0, t; }"
        : "=r"(a) : "l"(p));
    return a;
}

__device__ __forceinline__ void cp_async16(uint32_t dst, const void* src) {
    asm volatile("cp.async.cg.shared.global [%0], [%1], 16;"
                 :: "r"(dst), "l"(src) : "memory");
}
__device__ __forceinline__ void cp_commit() {
    asm volatile("cp.async.commit_group;" ::: "memory");
}
template <int N>
__device__ __forceinline__ void cp_wait() {
    asm volatile("cp.async.wait_group %0;" :: "n"(N) : "memory");
}

__device__ __forceinline__ void ldsm_x4(uint32_t* r, uint32_t addr) {
    asm volatile("ldmatrix.sync.aligned.m8n8.x4.shared.b16 {%0,%1,%2,%3}, [%4];"
                 : "=r"(r[0]), "=r"(r[1]), "=r"(r[2]), "=r"(r[3]) : "r"(addr));
}

__device__ __forceinline__ void ldsm_x4_trans(uint32_t* r, uint32_t addr) {
    asm volatile("ldmatrix.sync.aligned.m8n8.x4.trans.shared.b16 {%0,%1,%2,%3}, [%4];"
                 : "=r"(r[0]), "=r"(r[1]), "=r"(r[2]), "=r"(r[3]) : "r"(addr));
}

__device__ __forceinline__ void mma16816(float* c, const uint32_t* a, const uint32_t* b) {
    asm volatile(
        "mma.sync.aligned.m16n8k16.row.col.f32.f16.f16.f32 "
        "{%0,%1,%2,%3}, {%4,%5,%6,%7}, {%8,%9}, {%0,%1,%2,%3};"
        : "+f"(c[0]), "+f"(c[1]), "+f"(c[2]), "+f"(c[3])
        : "r"(a[0]), "r"(a[1]), "r"(a[2]), "r"(a[3]), "r"(b[0]), "r"(b[1]));
}

__device__ __forceinline__ uint32_t sw128(uint32_t off) {
    return off ^ ((off >> 3) & 0x70);
}

// ---------------- K0a: convert queries (single fp16) ------------------------
__global__ void convert_q_kernel(const float* __restrict__ q) {
    int idx = blockIdx.x * blockDim.x + threadIdx.x;   // float4 index
    float4 v = ((const float4*)q)[idx];
    __half h0 = __float2half(v.x), h1 = __float2half(v.y);
    __half h2 = __float2half(v.z), h3 = __float2half(v.w);
    uint2 hp;
    hp.x = (uint32_t)__half_as_ushort(h0) | ((uint32_t)__half_as_ushort(h1) << 16);
    hp.y = (uint32_t)__half_as_ushort(h2) | ((uint32_t)__half_as_ushort(h3) << 16);
    ((uint2*)g_Qh)[idx] = hp;
}

// ---------------- K0b: query norms ------------------------------------------
__global__ void qnorm_kernel(const float* __restrict__ q) {
    const int warp = threadIdx.x >> 5, lane = threadIdx.x & 31;
    const int row = blockIdx.x * 8 + warp;
    const float4* qp = (const float4*)(q + (size_t)row * Dn);
    float s = 0.f;
    #pragma unroll
    for (int i = 0; i < 8; i++) {
        float4 v = qp[lane + i * 32];
        s = fmaf(v.x, v.x, fmaf(v.y, v.y, fmaf(v.z, v.z, fmaf(v.w, v.w, s))));
    }
    #pragma unroll
    for (int o = 16; o > 0; o >>= 1) s += __shfl_xor_sync(0xffffffffu, s, o);
    if (lane == 0) g_QN[row] = sqrtf(s);
}

// ---------------- K0c: convert tokens (single fp16) -------------------------
__global__ void convert_tk_kernel(const float* __restrict__ tok) {
    size_t idx = (size_t)blockIdx.x * blockDim.x + threadIdx.x;   // float4 index
    float4 v = ((const float4*)tok)[idx];
    uint2 hp;
    __half h0 = __float2half(v.x), h1 = __float2half(v.y);
    __half h2 = __float2half(v.z), h3 = __float2half(v.w);
    hp.x = (uint32_t)__half_as_ushort(h0) | ((uint32_t)__half_as_ushort(h1) << 16);
    hp.y = (uint32_t)__half_as_ushort(h2) | ((uint32_t)__half_as_ushort(h3) << 16);
    ((uint2*)g_TH)[idx] = hp;
}

// ---------------- K2: warp-per-row softmax + dot + fp16 P -------------------
__global__ void softmax_kernel() {
    const int warp = threadIdx.x >> 5, lane = threadIdx.x & 31;
    const int row = blockIdx.x * 8 + warp;             // = b*Qn + q
    const float4* srow = (const float4*)(g_S + (size_t)row * Ln);

    float4 v[8];
    #pragma unroll
    for (int i = 0; i < 8; i++) v[i] = srow[lane + i * 32];

    float m = -INFINITY;
    #pragma unroll
    for (int i = 0; i < 8; i++)
        m = fmaxf(m, fmaxf(fmaxf(v[i].x, v[i].y), fmaxf(v[i].z, v[i].w)));
    #pragma unroll
    for (int o = 16; o > 0; o >>= 1) m = fmaxf(m, __shfl_xor_sync(0xffffffffu, m, o));

    float s = 0.f, ev = 0.f;
    float4 e[8];
    #pragma unroll
    for (int i = 0; i < 8; i++) {
        e[i].x = expf(v[i].x - m); e[i].y = expf(v[i].y - m);
        e[i].z = expf(v[i].z - m); e[i].w = expf(v[i].w - m);
        s  += e[i].x + e[i].y + e[i].z + e[i].w;
        ev += e[i].x * v[i].x + e[i].y * v[i].y + e[i].z * v[i].z + e[i].w * v[i].w;
    }
    #pragma unroll
    for (int o = 16; o > 0; o >>= 1) {
        s  += __shfl_xor_sync(0xffffffffu, s, o);
        ev += __shfl_xor_sync(0xffffffffu, ev, o);
    }
    const float inv = 1.0f / s;
    if (lane == 0) g_DOT[row] = 32.0f * inv * ev;      // dot(q, agg), exact identity

    uint2* pout = (uint2*)(g_Ph + (size_t)row * Ln);
    #pragma unroll
    for (int i = 0; i < 8; i++) {
        __half h0 = __float2half(e[i].x * inv);
        __half h1 = __float2half(e[i].y * inv);
        __half h2 = __float2half(e[i].z * inv);
        __half h3 = __float2half(e[i].w * inv);
        uint2 hp;
        hp.x = (uint32_t)__half_as_ushort(h0) | ((uint32_t)__half_as_ushort(h1) << 16);
        hp.y = (uint32_t)__half_as_ushort(h2) | ((uint32_t)__half_as_ushort(h3) << 16);
        pout[lane + i * 32] = hp;
    }
}

// ---------------- K1: GEMM1 (single fp16: Qh.T), tile 128x256 ---------------
// K chunks of 64. stage buf: A 16K + B 32K = 48K; x4 = 192K.
static constexpr uint32_t OFF_BH = 16384;
static constexpr uint32_t BUFSZ  = 49152;
static constexpr int GEMM1_SMEM = 196608;
static constexpr int NSTAGE = 4;

__global__ void __launch_bounds__(256, 1)
gemm1_kernel()
{
    extern __shared__ unsigned char smem[];
    const uint32_t sbase = smem_u32(smem);
    const int tid  = threadIdx.x;
    const int wid  = tid >> 5, lane = tid & 31;
    const int q0   = blockIdx.x * 128;
    const int n0   = blockIdx.y * 256;
    const int b    = blockIdx.z;

    const __half* Ah = g_Qh + (size_t)q0 * Dn;
    const __half* Bh = g_TH + (size_t)b * Ln * Dn + (size_t)n0 * Dn;
    float* Cg = g_S + ((size_t)b * Qn + q0) * Ln + n0;

    const int wm = wid >> 2, wn = wid & 3;              // warp tile 64x64
    const int arow  = wm * 64 + (lane & 7) + ((lane >> 3) & 1) * 8;
    const int acol8 = (lane >> 4) * 8;
    const int brow  = wn * 64 + (lane & 7) + (lane >> 4) * 8;
    const int bcol8 = ((lane >> 3) & 1) * 8;

    float c[4][8][4];
    #pragma unroll
    for (int mt = 0; mt < 4; mt++)
        #pragma unroll
        for (int nt = 0; nt < 8; nt++)
            #pragma unroll
            for (int i = 0; i < 4; i++) c[mt][nt][i] = 0.f;

    // prologue: stage chunks 0..2.  A: 1024 granules, B: 2048 granules.
    #pragma unroll
    for (int s = 0; s < NSTAGE - 1; s++) {
        uint32_t sb = sbase + s * BUFSZ;
        int k0 = s * 64;
        #pragma unroll
        for (int i = 0; i < 4; i++) {
            int g = tid + i * 256;
            int row = g >> 3, kg = g & 7;
            uint32_t sw = sw128((uint32_t)row * 128 + kg * 16);
            cp_async16(sb + sw, Ah + (size_t)row * 1024 + k0 + kg * 8);
        }
        #pragma unroll
        for (int i = 0; i < 8; i++) {
            int g = tid + i * 256;
            int row = g >> 3, kg = g & 7;
            uint32_t sw = sw128((uint32_t)row * 128 + kg * 16);
            cp_async16(sb + OFF_BH + sw, Bh + (size_t)row * 1024 + k0 + kg * 8);
        }
        cp_commit();
    }

    for (int kc = 0; kc < 16; kc++) {
        cp_wait<NSTAGE - 2>();
        __syncthreads();

        if (kc + NSTAGE - 1 < 16) {
            uint32_t sb = sbase + ((kc + NSTAGE - 1) & 3) * BUFSZ;
            int k0 = (kc + NSTAGE - 1) * 64;
            #pragma unroll
            for (int i = 0; i < 4; i++) {
                int g = tid + i * 256;
                int row = g >> 3, kg = g & 7;
                uint32_t sw = sw128((uint32_t)row * 128 + kg * 16);
                cp_async16(sb + sw, Ah + (size_t)row * 1024 + k0 + kg * 8);
            }
            #pragma unroll
            for (int i = 0; i < 8; i++) {
                int g = tid + i * 256;
                int row = g >> 3, kg = g & 7;
                uint32_t sw = sw128((uint32_t)row * 128 + kg * 16);
                cp_async16(sb + OFF_BH + sw, Bh + (size_t)row * 1024 + k0 + kg * 8);
            }
            cp_commit();
        } else {
            cp_commit();
        }

        const uint32_t base = sbase + (kc & 3) * BUFSZ;
        #pragma unroll
        for (int ks = 0; ks < 4; ks++) {
            const int kb = ks * 16;
            uint32_t ah[4][4], bh[8][2];
            #pragma unroll
            for (int mt = 0; mt < 4; mt++) {
                uint32_t sw = sw128((uint32_t)(arow + mt * 16) * 128 + (acol8 + kb) * 2);
                ldsm_x4(ah[mt], base + sw);
            }
            #pragma unroll
            for (int bt = 0; bt < 4; bt++) {
                uint32_t sw = sw128((uint32_t)(brow + bt * 16) * 128 + (bcol8 + kb) * 2);
                uint32_t t[4];
                ldsm_x4(t, base + OFF_BH + sw);
                bh[bt * 2][0] = t[0]; bh[bt * 2][1] = t[1];
                bh[bt * 2 + 1][0] = t[2]; bh[bt * 2 + 1][1] = t[3];
            }
            #pragma unroll
            for (int mt = 0; mt < 4; mt++)
                #pragma unroll
                for (int nt = 0; nt < 8; nt++)
                    mma16816(c[mt][nt], ah[mt], bh[nt]);
        }
    }

    const int r0 = lane >> 2, c0 = (lane & 3) * 2;
    #pragma unroll
    for (int mt = 0; mt < 4; mt++)
        #pragma unroll
        for (int nt = 0; nt < 8; nt++) {
            int row = wm * 64 + mt * 16 + r0;
            int col = wn * 64 + nt * 8 + c0;
            float2 v0 = make_float2(c[mt][nt][0] * 0.03125f, c[mt][nt][1] * 0.03125f);
            float2 v1 = make_float2(c[mt][nt][2] * 0.03125f, c[mt][nt][3] * 0.03125f);
            *(float2*)(Cg + (size_t)row * 1024 + col) = v0;
            *(float2*)(Cg + (size_t)(row + 8) * 1024 + col) = v1;
        }
}

// ---------------- K3: GEMM2 (fp16, B via ldmatrix.trans), tile 128x256 ------
// A tile: Ph 128(q) x 64(l), K-major, 16K. B tile: TH 64(l) x 256(d), 32K.
// B smem: row = l (64 rows x 512B); granule g (0..31) in row stored at
//   ((g & ~7) | ((g ^ row) & 7)) * 16  -> conflict-free trans-ldmatrix.
static constexpr uint32_t OFF2_B = 16384;
static constexpr uint32_t BUFSZ2 = 49152;
static constexpr int GEMM2_SMEM = 196608;

__device__ __forceinline__ uint32_t swB(uint32_t row, uint32_t nbyte) {
    uint32_t g = nbyte >> 4;
    return row * 512 + (((g & ~7u) | ((g ^ row) & 7)) << 4);
}

__global__ void __launch_bounds__(256, 1)
gemm2_kernel()
{
    extern __shared__ unsigned char smem[];
    const uint32_t sbase = smem_u32(smem);
    const int tid  = threadIdx.x;
    const int wid  = tid >> 5, lane = tid & 31;
    const int q0   = blockIdx.x * 128;
    const int n0   = blockIdx.y * 256;     // d-slab
    const int b    = blockIdx.z;

    const __half* Ah = g_Ph + ((size_t)b * Qn + q0) * Ln;
    const __half* Bh = g_TH + (size_t)b * Ln * Dn;   // [l][d]

    const int wm = wid >> 2, wn = wid & 3;              // warp tile 64x64
    const int arow  = wm * 64 + (lane & 7) + ((lane >> 3) & 1) * 8;
    const int acol8 = (lane >> 4) * 8;

    const int t_r    = lane & 7;
    const int t_krow = ((lane >> 3) & 1) * 8 + t_r;
    const int t_nb   = (lane >> 4) * 16;

    float c[4][8][4];
    #pragma unroll
    for (int mt = 0; mt < 4; mt++)
        #pragma unroll
        for (int nt = 0; nt < 8; nt++)
            #pragma unroll
            for (int i = 0; i < 4; i++) c[mt][nt][i] = 0.f;

    // prologue: stage chunks 0..2.  A: 1024 granules, B: 2048 granules.
    #pragma unroll
    for (int s = 0; s < NSTAGE - 1; s++) {
        uint32_t sb = sbase + s * BUFSZ2;
        int k0 = s * 64;
        #pragma unroll
        for (int i = 0; i < 4; i++) {
            int g = tid + i * 256;
            int row = g >> 3, kg = g & 7;
            uint32_t sw = sw128((uint32_t)row * 128 + kg * 16);
            cp_async16(sb + sw, Ah + (size_t)row * 1024 + k0 + kg * 8);
        }
        #pragma unroll
        for (int i = 0; i < 8; i++) {
            int g = tid + i * 256;
            int row = g >> 5, kg = g & 31;               // 64 rows x 32 granules
            cp_async16(sb + OFF2_B + swB(row, kg * 16),
                       Bh + (size_t)(k0 + row) * 1024 + n0 + kg * 8);
        }
        cp_commit();
    }

    for (int kc = 0; kc < 16; kc++) {
        cp_wait<NSTAGE - 2>();
        __syncthreads();

        if (kc + NSTAGE - 1 < 16) {
            uint32_t sb = sbase + ((kc + NSTAGE - 1) & 3) * BUFSZ2;
            int k0 = (kc + NSTAGE - 1) * 64;
            #pragma unroll
            for (int i = 0; i < 4; i++) {
                int g = tid + i * 256;
                int row = g >> 3, kg = g & 7;
                uint32_t sw = sw128((uint32_t)row * 128 + kg * 16);
                cp_async16(sb + sw, Ah + (size_t)row * 1024 + k0 + kg * 8);
            }
            #pragma unroll
            for (int i = 0; i < 8; i++) {
                int g = tid + i * 256;
                int row = g >> 5, kg = g & 31;
                cp_async16(sb + OFF2_B + swB(row, kg * 16),
                           Bh + (size_t)(k0 + row) * 1024 + n0 + kg * 8);
            }
            cp_commit();
        } else {
            cp_commit();
        }

        const uint32_t base = sbase + (kc & 3) * BUFSZ2;
        #pragma unroll
        for (int ks = 0; ks < 4; ks++) {
            const int kb = ks * 16;
            uint32_t ah[4][4], bh[8][2];
            #pragma unroll
            for (int mt = 0; mt < 4; mt++) {
                uint32_t sw = sw128((uint32_t)(arow + mt * 16) * 128 + (acol8 + kb) * 2);
                ldsm_x4(ah[mt], base + sw);
            }
            #pragma unroll
            for (int bt = 0; bt < 4; bt++) {
                uint32_t row = kb + t_krow;
                uint32_t nb  = (wn * 64 + bt * 16) * 2 + t_nb;
                uint32_t t[4];
                ldsm_x4_trans(t, base + OFF2_B + swB(row, nb));
                bh[bt * 2][0] = t[0]; bh[bt * 2][1] = t[1];
                bh[bt * 2 + 1][0] = t[2]; bh[bt * 2 + 1][1] = t[3];
            }
            #pragma unroll
            for (int mt = 0; mt < 4; mt++)
                #pragma unroll
                for (int nt = 0; nt < 8; nt++)
                    mma16816(c[mt][nt], ah[mt], bh[nt]);
        }
    }

    __syncthreads();   // all warps done reading staging before smem reuse

    // ---- epilogue: per-row sum of squares, deterministic reduction ----
    float* red = (float*)smem;                 // aliases staging (done with it)
    const int r0 = lane >> 2;
    #pragma unroll
    for (int mt = 0; mt < 4; mt++) {
        float s0 = 0.f, s1 = 0.f;
        #pragma unroll
        for (int nt = 0; nt < 8; nt++) {
            s0 = fmaf(c[mt][nt][0], c[mt][nt][0], fmaf(c[mt][nt][1], c[mt][nt][1], s0));
            s1 = fmaf(c[mt][nt][2], c[mt][nt][2], fmaf(c[mt][nt][3], c[mt][nt][3], s1));
        }
        s0 += __shfl_xor_sync(0xffffffffu, s0, 1);
        s0 += __shfl_xor_sync(0xffffffffu, s0, 2);
        s1 += __shfl_xor_sync(0xffffffffu, s1, 1);
        s1 += __shfl_xor_sync(0xffffffffu, s1, 2);
        if ((lane & 3) == 0) {
            red[wn * 128 + wm * 64 + mt * 16 + r0]     = s0;
            red[wn * 128 + wm * 64 + mt * 16 + r0 + 8] = s1;
        }
    }
    __syncthreads();
    if (tid < 128) {
        float v = red[tid] + red[128 + tid] + red[256 + tid] + red[384 + tid];
        g_A2P[((size_t)b * 4 + blockIdx.y) * Qn + q0 + tid] = v;
    }
}

// ---------------- K4: final logits ------------------------------------------
__global__ void final_kernel(float* __restrict__ out) {
    const int idx = blockIdx.x * blockDim.x + threadIdx.x;   // row = b*512 + q
    const int b = idx >> 9, q = idx & 511;
    float a2 = 0.f;
    #pragma unroll
    for (int nt = 0; nt < 4; nt++)
        a2 += g_A2P[((size_t)b * 4 + nt) * Qn + q];
    float dn = fmaxf(g_QN[q], 1e-12f) * fmaxf(sqrtf(a2), 1e-12f);
    out[(size_t)q * Bn + b] = g_DOT[idx] / dn;
}

// ---------------- launch ----------------------------------------------------
extern "C" void kernel_launch(void* const* d_in, const int* in_sizes, int n_in,
                              void* d_out, int out_size)
{
    const float* queries = (const float*)d_in[0];   // [512,1024]
    const float* tokens  = (const float*)d_in[1];   // [64,1024,1024]
    float* out = (float*)d_out;                     // [512,64]

    cudaFuncSetAttribute(gemm1_kernel,
                         cudaFuncAttributeMaxDynamicSharedMemorySize, GEMM1_SMEM);
    cudaFuncSetAttribute(gemm2_kernel,
                         cudaFuncAttributeMaxDynamicSharedMemorySize, GEMM2_SMEM);

    convert_q_kernel<<<512, 256>>>(queries);
    qnorm_kernel<<<64, 256>>>(queries);
    convert_tk_kernel<<<65536, 256>>>(tokens);
    gemm1_kernel<<<dim3(Qn / 128, Ln / 256, Bn), 256, GEMM1_SMEM>>>();
    softmax_kernel<<<Bn * Qn / 8, 256>>>();
    gemm2_kernel<<<dim3(Qn / 128, Dn / 256, Bn), 256, GEMM2_SMEM>>>();
    final_kernel<<<(Bn * Qn) / 256, 256>>>(out);
}

// round 11
// speedup vs baseline: 10.3008x; 1.0611x over previous
#include <cuda_runtime.h>
#include <cuda_fp16.h>
#include <cstdint>
#include <math.h>

// SimilarityLogit on GB300 via mma.sync (HMMA) fp16 GEMMs, fp32 accumulate.
//   queries      : [Q=512, D=1024]  fp32      (d_in[0])
//   local_tokens : [B=64, L=1024, D=1024] fp32 (d_in[1])
//   out          : [Q=512, B=64]   fp32  (out[q*64+b])
//
// Math: S = qT^t/32 ; P = softmax(S) ; agg = P T
//   out = dot(q,agg)/(max(||q||,eps) max(||agg||,eps))
// Identity: dot(q,agg) = 32 * sum_l P[l] S[l]  -> computed in softmax kernel.
// GEMM2 only supplies ||agg||^2. Tokens stored ONCE fp16 [l][d]; GEMM1 uses
// them K-major, GEMM2 via ldmatrix.trans. Q single fp16.
// This round: CTA 128x128, 128 threads (4 warps, 64x64 warp tile, ratio 4.0),
// 3-stage x 32KB smem -> 2 CTAs/SM so chunk-boundary syncs overlap across CTAs.

static constexpr int Qn = 512, Dn = 1024, Ln = 1024, Bn = 64;

// ---------------- scratch (device globals; no runtime allocation) ----------
__device__ __half g_Qh[(size_t)Qn * Dn];
__device__ __half g_TH[(size_t)Bn * Ln * Dn];          // tokens fp16 [b][l][d]
__device__ float  g_S[(size_t)Bn * Qn * Ln];
__device__ __half g_Ph[(size_t)Bn * Qn * Ln];
__device__ float  g_DOT[(size_t)Bn * Qn];
__device__ float  g_A2P[(size_t)Bn * 8 * Qn];          // per-(b, d-slab) row partials
__device__ float  g_QN[Qn];

// ---------------- PTX helpers ----------------------------------------------
__device__ __forceinline__ uint32_t smem_u32(const void* p) {
    uint32_t a;
    asm("{ .reg .u64 t; cvta.to.shared.u64 t, %1; cvt.u32.u64 %0, t; }"
        : "=r"(a) : "l"(p));
    return a;
}

__device__ __forceinline__ void cp_async16(uint32_t dst, const void* src) {
    asm volatile("cp.async.cg.shared.global [%0], [%1], 16;"
                 :: "r"(dst), "l"(src) : "memory");
}
__device__ __forceinline__ void cp_commit() {
    asm volatile("cp.async.commit_group;" ::: "memory");
}
template <int N>
__device__ __forceinline__ void cp_wait() {
    asm volatile("cp.async.wait_group %0;" :: "n"(N) : "memory");
}

__device__ __forceinline__ void ldsm_x4(uint32_t* r, uint32_t addr) {
    asm volatile("ldmatrix.sync.aligned.m8n8.x4.shared.b16 {%0,%1,%2,%3}, [%4];"
                 : "=r"(r[0]), "=r"(r[1]), "=r"(r[2]), "=r"(r[3]) : "r"(addr));
}

__device__ __forceinline__ void ldsm_x4_trans(uint32_t* r, uint32_t addr) {
    asm volatile("ldmatrix.sync.aligned.m8n8.x4.trans.shared.b16 {%0,%1,%2,%3}, [%4];"
                 : "=r"(r[0]), "=r"(r[1]), "=r"(r[2]), "=r"(r[3]) : "r"(addr));
}

__device__ __forceinline__ void mma16816(float* c, const uint32_t* a, const uint32_t* b) {
    asm volatile(
        "mma.sync.aligned.m16n8k16.row.col.f32.f16.f16.f32 "
        "{%0,%1,%2,%3}, {%4,%5,%6,%7}, {%8,%9}, {%0,%1,%2,%3};"
        : "+f"(c[0]), "+f"(c[1]), "+f"(c[2]), "+f"(c[3])
        : "r"(a[0]), "r"(a[1]), "r"(a[2]), "r"(a[3]), "r"(b[0]), "r"(b[1]));
}

__device__ __forceinline__ uint32_t sw128(uint32_t off) {
    return off ^ ((off >> 3) & 0x70);
}

// ---------------- K0a: convert queries (single fp16) ------------------------
__global__ void convert_q_kernel(const float* __restrict__ q) {
    int idx = blockIdx.x * blockDim.x + threadIdx.x;   // float4 index
    float4 v = ((const float4*)q)[idx];
    __half h0 = __float2half(v.x), h1 = __float2half(v.y);
    __half h2 = __float2half(v.z), h3 = __float2half(v.w);
    uint2 hp;
    hp.x = (uint32_t)__half_as_ushort(h0) | ((uint32_t)__half_as_ushort(h1) << 16);
    hp.y = (uint32_t)__half_as_ushort(h2) | ((uint32_t)__half_as_ushort(h3) << 16);
    ((uint2*)g_Qh)[idx] = hp;
}

// ---------------- K0b: query norms ------------------------------------------
__global__ void qnorm_kernel(const float* __restrict__ q) {
    const int warp = threadIdx.x >> 5, lane = threadIdx.x & 31;
    const int row = blockIdx.x * 8 + warp;
    const float4* qp = (const float4*)(q + (size_t)row * Dn);
    float s = 0.f;
    #pragma unroll
    for (int i = 0; i < 8; i++) {
        float4 v = qp[lane + i * 32];
        s = fmaf(v.x, v.x, fmaf(v.y, v.y, fmaf(v.z, v.z, fmaf(v.w, v.w, s))));
    }
    #pragma unroll
    for (int o = 16; o > 0; o >>= 1) s += __shfl_xor_sync(0xffffffffu, s, o);
    if (lane == 0) g_QN[row] = sqrtf(s);
}

// ---------------- K0c: convert tokens (single fp16) -------------------------
__global__ void convert_tk_kernel(const float* __restrict__ tok) {
    size_t idx = (size_t)blockIdx.x * blockDim.x + threadIdx.x;   // float4 index
    float4 v = ((const float4*)tok)[idx];
    uint2 hp;
    __half h0 = __float2half(v.x), h1 = __float2half(v.y);
    __half h2 = __float2half(v.z), h3 = __float2half(v.w);
    hp.x = (uint32_t)__half_as_ushort(h0) | ((uint32_t)__half_as_ushort(h1) << 16);
    hp.y = (uint32_t)__half_as_ushort(h2) | ((uint32_t)__half_as_ushort(h3) << 16);
    ((uint2*)g_TH)[idx] = hp;
}

// ---------------- K2: warp-per-row softmax + dot + fp16 P -------------------
__global__ void softmax_kernel() {
    const int warp = threadIdx.x >> 5, lane = threadIdx.x & 31;
    const int row = blockIdx.x * 8 + warp;             // = b*Qn + q
    const float4* srow = (const float4*)(g_S + (size_t)row * Ln);

    float4 v[8];
    #pragma unroll
    for (int i = 0; i < 8; i++) v[i] = srow[lane + i * 32];

    float m = -INFINITY;
    #pragma unroll
    for (int i = 0; i < 8; i++)
        m = fmaxf(m, fmaxf(fmaxf(v[i].x, v[i].y), fmaxf(v[i].z, v[i].w)));
    #pragma unroll
    for (int o = 16; o > 0; o >>= 1) m = fmaxf(m, __shfl_xor_sync(0xffffffffu, m, o));

    float s = 0.f, ev = 0.f;
    float4 e[8];
    #pragma unroll
    for (int i = 0; i < 8; i++) {
        e[i].x = expf(v[i].x - m); e[i].y = expf(v[i].y - m);
        e[i].z = expf(v[i].z - m); e[i].w = expf(v[i].w - m);
        s  += e[i].x + e[i].y + e[i].z + e[i].w;
        ev += e[i].x * v[i].x + e[i].y * v[i].y + e[i].z * v[i].z + e[i].w * v[i].w;
    }
    #pragma unroll
    for (int o = 16; o > 0; o >>= 1) {
        s  += __shfl_xor_sync(0xffffffffu, s, o);
        ev += __shfl_xor_sync(0xffffffffu, ev, o);
    }
    const float inv = 1.0f / s;
    if (lane == 0) g_DOT[row] = 32.0f * inv * ev;      // dot(q, agg), exact identity

    uint2* pout = (uint2*)(g_Ph + (size_t)row * Ln);
    #pragma unroll
    for (int i = 0; i < 8; i++) {
        __half h0 = __float2half(e[i].x * inv);
        __half h1 = __float2half(e[i].y * inv);
        __half h2 = __float2half(e[i].z * inv);
        __half h3 = __float2half(e[i].w * inv);
        uint2 hp;
        hp.x = (uint32_t)__half_as_ushort(h0) | ((uint32_t)__half_as_ushort(h1) << 16);
        hp.y = (uint32_t)__half_as_ushort(h2) | ((uint32_t)__half_as_ushort(h3) << 16);
        pout[lane + i * 32] = hp;
    }
}

// ---------------- K1: GEMM1 (single fp16: Qh.T), CTA 128x128, 128 thr -------
// K chunks of 64. stage buf: A 16K + B 16K = 32K; x3 = 96K. 2 CTAs/SM.
static constexpr uint32_t OFF_BH = 16384;
static constexpr uint32_t BUFSZ  = 32768;
static constexpr int GEMM_SMEM = 98304;
static constexpr int NSTAGE = 3;

__global__ void __launch_bounds__(128, 2)
gemm1_kernel()
{
    extern __shared__ unsigned char smem[];
    const uint32_t sbase = smem_u32(smem);
    const int tid  = threadIdx.x;
    const int wid  = tid >> 5, lane = tid & 31;
    const int q0   = blockIdx.x * 128;
    const int n0   = blockIdx.y * 128;
    const int b    = blockIdx.z;

    const __half* Ah = g_Qh + (size_t)q0 * Dn;
    const __half* Bh = g_TH + (size_t)b * Ln * Dn + (size_t)n0 * Dn;
    float* Cg = g_S + ((size_t)b * Qn + q0) * Ln + n0;

    const int wm = wid >> 1, wn = wid & 1;              // 2x2 warps, 64x64 tile
    const int arow  = wm * 64 + (lane & 7) + ((lane >> 3) & 1) * 8;
    const int acol8 = (lane >> 4) * 8;
    const int brow  = wn * 64 + (lane & 7) + (lane >> 4) * 8;
    const int bcol8 = ((lane >> 3) & 1) * 8;

    float c[4][8][4];
    #pragma unroll
    for (int mt = 0; mt < 4; mt++)
        #pragma unroll
        for (int nt = 0; nt < 8; nt++)
            #pragma unroll
            for (int i = 0; i < 4; i++) c[mt][nt][i] = 0.f;

    // prologue: stage chunks 0..1.  A: 1024 granules, B: 1024 granules.
    #pragma unroll
    for (int s = 0; s < NSTAGE - 1; s++) {
        uint32_t sb = sbase + s * BUFSZ;
        int k0 = s * 64;
        #pragma unroll
        for (int i = 0; i < 8; i++) {
            int g = tid + i * 128;
            int row = g >> 3, kg = g & 7;
            uint32_t sw = sw128((uint32_t)row * 128 + kg * 16);
            cp_async16(sb + sw,          Ah + (size_t)row * 1024 + k0 + kg * 8);
            cp_async16(sb + OFF_BH + sw, Bh + (size_t)row * 1024 + k0 + kg * 8);
        }
        cp_commit();
    }

    int bufc = 0, bufs = NSTAGE - 1;
    for (int kc = 0; kc < 16; kc++) {
        cp_wait<NSTAGE - 2>();
        __syncthreads();

        if (kc + NSTAGE - 1 < 16) {
            uint32_t sb = sbase + bufs * BUFSZ;
            int k0 = (kc + NSTAGE - 1) * 64;
            #pragma unroll
            for (int i = 0; i < 8; i++) {
                int g = tid + i * 128;
                int row = g >> 3, kg = g & 7;
                uint32_t sw = sw128((uint32_t)row * 128 + kg * 16);
                cp_async16(sb + sw,          Ah + (size_t)row * 1024 + k0 + kg * 8);
                cp_async16(sb + OFF_BH + sw, Bh + (size_t)row * 1024 + k0 + kg * 8);
            }
            cp_commit();
        } else {
            cp_commit();
        }
        if (++bufs == NSTAGE) bufs = 0;

        const uint32_t base = sbase + bufc * BUFSZ;
        if (++bufc == NSTAGE) bufc = 0;
        #pragma unroll
        for (int ks = 0; ks < 4; ks++) {
            const int kb = ks * 16;
            uint32_t ah[4][4], bh[8][2];
            #pragma unroll
            for (int mt = 0; mt < 4; mt++) {
                uint32_t sw = sw128((uint32_t)(arow + mt * 16) * 128 + (acol8 + kb) * 2);
                ldsm_x4(ah[mt], base + sw);
            }
            #pragma unroll
            for (int bt = 0; bt < 4; bt++) {
                uint32_t sw = sw128((uint32_t)(brow + bt * 16) * 128 + (bcol8 + kb) * 2);
                uint32_t t[4];
                ldsm_x4(t, base + OFF_BH + sw);
                bh[bt * 2][0] = t[0]; bh[bt * 2][1] = t[1];
                bh[bt * 2 + 1][0] = t[2]; bh[bt * 2 + 1][1] = t[3];
            }
            #pragma unroll
            for (int mt = 0; mt < 4; mt++)
                #pragma unroll
                for (int nt = 0; nt < 8; nt++)
                    mma16816(c[mt][nt], ah[mt], bh[nt]);
        }
    }

    const int r0 = lane >> 2, c0 = (lane & 3) * 2;
    #pragma unroll
    for (int mt = 0; mt < 4; mt++)
        #pragma unroll
        for (int nt = 0; nt < 8; nt++) {
            int row = wm * 64 + mt * 16 + r0;
            int col = wn * 64 + nt * 8 + c0;
            float2 v0 = make_float2(c[mt][nt][0] * 0.03125f, c[mt][nt][1] * 0.03125f);
            float2 v1 = make_float2(c[mt][nt][2] * 0.03125f, c[mt][nt][3] * 0.03125f);
            *(float2*)(Cg + (size_t)row * 1024 + col) = v0;
            *(float2*)(Cg + (size_t)(row + 8) * 1024 + col) = v1;
        }
}

// ---------------- K3: GEMM2 (fp16, B via ldmatrix.trans), CTA 128x128 -------
// A tile: Ph 128(q) x 64(l), 16K. B tile: TH 64(l) x 128(d), 16K. x3 stages.
// B smem: row = l (64 rows x 256B); granule g (0..15) stored at
//   (g&8)*16 + ((g^row)&7)*16 -> conflict-free trans-ldmatrix.
static constexpr uint32_t OFF2_B = 16384;
static constexpr uint32_t BUFSZ2 = 32768;

__device__ __forceinline__ uint32_t swB(uint32_t row, uint32_t nbyte) {
    uint32_t g = nbyte >> 4;
    return row * 256 + (g & 8) * 16 + (((g ^ row) & 7) << 4);
}

__global__ void __launch_bounds__(128, 2)
gemm2_kernel()
{
    extern __shared__ unsigned char smem[];
    const uint32_t sbase = smem_u32(smem);
    const int tid  = threadIdx.x;
    const int wid  = tid >> 5, lane = tid & 31;
    const int q0   = blockIdx.x * 128;
    const int n0   = blockIdx.y * 128;     // d-slab
    const int b    = blockIdx.z;

    const __half* Ah = g_Ph + ((size_t)b * Qn + q0) * Ln;
    const __half* Bh = g_TH + (size_t)b * Ln * Dn;   // [l][d]

    const int wm = wid >> 1, wn = wid & 1;              // 2x2 warps, 64x64 tile
    const int arow  = wm * 64 + (lane & 7) + ((lane >> 3) & 1) * 8;
    const int acol8 = (lane >> 4) * 8;

    const int t_r    = lane & 7;
    const int t_krow = ((lane >> 3) & 1) * 8 + t_r;
    const int t_nb   = (lane >> 4) * 16;

    float c[4][8][4];
    #pragma unroll
    for (int mt = 0; mt < 4; mt++)
        #pragma unroll
        for (int nt = 0; nt < 8; nt++)
            #pragma unroll
            for (int i = 0; i < 4; i++) c[mt][nt][i] = 0.f;

    // prologue: stage chunks 0..1.  A: 1024 granules, B: 1024 granules.
    #pragma unroll
    for (int s = 0; s < NSTAGE - 1; s++) {
        uint32_t sb = sbase + s * BUFSZ2;
        int k0 = s * 64;
        #pragma unroll
        for (int i = 0; i < 8; i++) {
            int g = tid + i * 128;
            {   // A: 128 rows x 8 granules
                int row = g >> 3, kg = g & 7;
                uint32_t sw = sw128((uint32_t)row * 128 + kg * 16);
                cp_async16(sb + sw, Ah + (size_t)row * 1024 + k0 + kg * 8);
            }
            {   // B: 64 rows x 16 granules
                int row = g >> 4, kg = g & 15;
                cp_async16(sb + OFF2_B + swB(row, kg * 16),
                           Bh + (size_t)(k0 + row) * 1024 + n0 + kg * 8);
            }
        }
        cp_commit();
    }

    int bufc = 0, bufs = NSTAGE - 1;
    for (int kc = 0; kc < 16; kc++) {
        cp_wait<NSTAGE - 2>();
        __syncthreads();

        if (kc + NSTAGE - 1 < 16) {
            uint32_t sb = sbase + bufs * BUFSZ2;
            int k0 = (kc + NSTAGE - 1) * 64;
            #pragma unroll
            for (int i = 0; i < 8; i++) {
                int g = tid + i * 128;
                {
                    int row = g >> 3, kg = g & 7;
                    uint32_t sw = sw128((uint32_t)row * 128 + kg * 16);
                    cp_async16(sb + sw, Ah + (size_t)row * 1024 + k0 + kg * 8);
                }
                {
                    int row = g >> 4, kg = g & 15;
                    cp_async16(sb + OFF2_B + swB(row, kg * 16),
                               Bh + (size_t)(k0 + row) * 1024 + n0 + kg * 8);
                }
            }
            cp_commit();
        } else {
            cp_commit();
        }
        if (++bufs == NSTAGE) bufs = 0;

        const uint32_t base = sbase + bufc * BUFSZ2;
        if (++bufc == NSTAGE) bufc = 0;
        #pragma unroll
        for (int ks = 0; ks < 4; ks++) {
            const int kb = ks * 16;
            uint32_t ah[4][4], bh[8][2];
            #pragma unroll
            for (int mt = 0; mt < 4; mt++) {
                uint32_t sw = sw128((uint32_t)(arow + mt * 16) * 128 + (acol8 + kb) * 2);
                ldsm_x4(ah[mt], base + sw);
            }
            #pragma unroll
            for (int bt = 0; bt < 4; bt++) {
                uint32_t row = kb + t_krow;
                uint32_t nb  = (wn * 64 + bt * 16) * 2 + t_nb;
                uint32_t t[4];
                ldsm_x4_trans(t, base + OFF2_B + swB(row, nb));
                bh[bt * 2][0] = t[0]; bh[bt * 2][1] = t[1];
                bh[bt * 2 + 1][0] = t[2]; bh[bt * 2 + 1][1] = t[3];
            }
            #pragma unroll
            for (int mt = 0; mt < 4; mt++)
                #pragma unroll
                for (int nt = 0; nt < 8; nt++)
                    mma16816(c[mt][nt], ah[mt], bh[nt]);
        }
    }

    __syncthreads();   // all warps done reading staging before smem reuse

    // ---- epilogue: per-row sum of squares, deterministic reduction ----
    float* red = (float*)smem;                 // [2][128] floats
    const int r0 = lane >> 2;
    #pragma unroll
    for (int mt = 0; mt < 4; mt++) {
        float s0 = 0.f, s1 = 0.f;
        #pragma unroll
        for (int nt = 0; nt < 8; nt++) {
            s0 = fmaf(c[mt][nt][0], c[mt][nt][0], fmaf(c[mt][nt][1], c[mt][nt][1], s0));
            s1 = fmaf(c[mt][nt][2], c[mt][nt][2], fmaf(c[mt][nt][3], c[mt][nt][3], s1));
        }
        s0 += __shfl_xor_sync(0xffffffffu, s0, 1);
        s0 += __shfl_xor_sync(0xffffffffu, s0, 2);
        s1 += __shfl_xor_sync(0xffffffffu, s1, 1);
        s1 += __shfl_xor_sync(0xffffffffu, s1, 2);
        if ((lane & 3) == 0) {
            red[wn * 128 + wm * 64 + mt * 16 + r0]     = s0;
            red[wn * 128 + wm * 64 + mt * 16 + r0 + 8] = s1;
        }
    }
    __syncthreads();
    {
        float v = red[tid] + red[128 + tid];
        g_A2P[((size_t)b * 8 + blockIdx.y) * Qn + q0 + tid] = v;
    }
}

// ---------------- K4: final logits ------------------------------------------
__global__ void final_kernel(float* __restrict__ out) {
    const int idx = blockIdx.x * blockDim.x + threadIdx.x;   // row = b*512 + q
    const int b = idx >> 9, q = idx & 511;
    float a2 = 0.f;
    #pragma unroll
    for (int nt = 0; nt < 8; nt++)
        a2 += g_A2P[((size_t)b * 8 + nt) * Qn + q];
    float dn = fmaxf(g_QN[q], 1e-12f) * fmaxf(sqrtf(a2), 1e-12f);
    out[(size_t)q * Bn + b] = g_DOT[idx] / dn;
}

// ---------------- launch ----------------------------------------------------
extern "C" void kernel_launch(void* const* d_in, const int* in_sizes, int n_in,
                              void* d_out, int out_size)
{
    const float* queries = (const float*)d_in[0];   // [512,1024]
    const float* tokens  = (const float*)d_in[1];   // [64,1024,1024]
    float* out = (float*)d_out;                     // [512,64]

    cudaFuncSetAttribute(gemm1_kernel,
                         cudaFuncAttributeMaxDynamicSharedMemorySize, GEMM_SMEM);
    cudaFuncSetAttribute(gemm2_kernel,
                         cudaFuncAttributeMaxDynamicSharedMemorySize, GEMM_SMEM);

    convert_q_kernel<<<512, 256>>>(queries);
    qnorm_kernel<<<64, 256>>>(queries);
    convert_tk_kernel<<<65536, 256>>>(tokens);
    gemm1_kernel<<<dim3(Qn / 128, Ln / 128, Bn), 128, GEMM_SMEM>>>();
    softmax_kernel<<<Bn * Qn / 8, 256>>>();
    gemm2_kernel<<<dim3(Qn / 128, Dn / 128, Bn), 128, GEMM_SMEM>>>();
    final_kernel<<<(Bn * Qn) / 256, 256>>>(out);
}